// round 10
// baseline (speedup 1.0000x reference)
#include <cuda_runtime.h>
#include <cuda_bf16.h>

// Problem constants (fixed by the reference)
#define NN 100000
#define EE 1600000
#define ENQ 1700000        // EE + NN (edges + self loops)
#define GGR 128
#define KDIM 329
#define HC 256             // H*C = 4*64

// GEMM tiling: single pass over all 256 columns
#define BM 64
#define BN 256
#define BK 32
#define KPAD 352           // KDIM padded to NIT*BK (11*32), 16B-aligned rows
#define NIT (KPAD / BK)    // 11

// ---------------- static device scratch (no cudaMalloc allowed) ----------------
__device__ __nv_bfloat162 d_xpb[(size_t)NN * HC / 2]; // [N, H*C] projected feats, bf16
__device__ __nv_bfloat16  d_xb[(size_t)NN * KPAD];    // x in bf16, zero-padded cols
__device__ __nv_bfloat16  d_Wb[KDIM * HC];            // W in bf16 (k_wprep)
__device__ float4 d_asrc[NN];             // a_src[n][4]
__device__ float4 d_adst[NN];             // a_dst[n][4]
__device__ int    d_slot[ENQ];            // CSR slot: src node id
__device__ int    d_deg[NN];              // zero at rest; reset by k_scan1
__device__ int    d_rowptr[NN + 1];       // rebuilt every run by scans
__device__ int    d_bsum[128];
__device__ int    d_boff[128];
__device__ float  d_gsum[GGR * 64];       // zero at rest; reset by k_mlp
__device__ int    d_gcnt[GGR];            // zero at rest; reset by k_mlp
__device__ int    d_flag32;               // 1 if int32 inputs; reset by k_mlp

// ---------------- helpers ----------------
__device__ __forceinline__ int2 edge_sd(const void* ei, int e) {
    if (d_flag32) {
        const int* p = (const int*)ei;
        return make_int2(p[e], p[EE + e]);
    } else {
        const long long* p = (const long long*)ei;
        return make_int2((int)p[e], (int)p[EE + e]);
    }
}
__device__ __forceinline__ int batch_of(const void* b, int n) {
    if (d_flag32) return ((const int*)b)[n];
    return (int)((const long long*)b)[n];
}
__device__ __forceinline__ float lrelu(float v) { return v > 0.f ? v : 0.2f * v; }
__device__ __forceinline__ float2 bf2f(__nv_bfloat162 v) { return __bfloat1622float2(v); }
__device__ __forceinline__ unsigned packbf(float a, float b) {
    __nv_bfloat162 p = __float22bfloat162_rn(make_float2(a, b));
    return *(unsigned*)&p;
}
__device__ __forceinline__ void cpa16(unsigned dst, const void* src, bool p) {
    int sz = p ? 16 : 0;
    asm volatile("cp.async.cg.shared.global [%0], [%1], 16, %2;\n"
                 :: "r"(dst), "l"(src), "r"(sz));
}
__device__ __forceinline__ void ldsm_x4(unsigned& r0, unsigned& r1, unsigned& r2, unsigned& r3,
                                        unsigned addr) {
    asm volatile("ldmatrix.sync.aligned.m8n8.x4.shared.b16 {%0,%1,%2,%3}, [%4];"
                 : "=r"(r0), "=r"(r1), "=r"(r2), "=r"(r3) : "r"(addr));
}
__device__ __forceinline__ void ldsm_x4t(unsigned& r0, unsigned& r1, unsigned& r2, unsigned& r3,
                                         unsigned addr) {
    asm volatile("ldmatrix.sync.aligned.m8n8.x4.trans.shared.b16 {%0,%1,%2,%3}, [%4];"
                 : "=r"(r0), "=r"(r1), "=r"(r2), "=r"(r3) : "r"(addr));
}
__device__ __forceinline__ void mma_bf16(float4& d,
                                         unsigned a0, unsigned a1, unsigned a2, unsigned a3,
                                         unsigned b0, unsigned b1) {
    asm volatile(
        "mma.sync.aligned.m16n8k16.row.col.f32.bf16.bf16.f32 "
        "{%0,%1,%2,%3}, {%4,%5,%6,%7}, {%8,%9}, {%0,%1,%2,%3};\n"
        : "+f"(d.x), "+f"(d.y), "+f"(d.z), "+f"(d.w)
        : "r"(a0), "r"(a1), "r"(a2), "r"(a3), "r"(b0), "r"(b1));
}

// ---------------- kernels ----------------
// Detect int32 vs int64: in an int64 LE array the odd 32-bit words (hi) are all 0.
// d_flag32 is 0 at rest (reset by k_mlp at the end of every run).
__global__ void k_detect(const unsigned* __restrict__ ei) {
    int i = blockIdx.x * blockDim.x + threadIdx.x;
    bool nz = false;
    for (int e = i; e < EE; e += gridDim.x * blockDim.x)
        nz |= (ei[2 * e + 1] != 0u);
    unsigned b = __ballot_sync(0xffffffffu, nz);
    if ((threadIdx.x & 31) == 0 && b) atomicOr(&d_flag32, 1);
}

// x fp32 -> bf16, padded to KPAD cols. One 16B chunk (8 cols) per thread.
__global__ void k_xprep(const float* __restrict__ x) {
    long long idx = (long long)blockIdx.x * 256 + threadIdx.x;
    if (idx >= (long long)NN * (KPAD / 8)) return;
    int r = (int)(idx / (KPAD / 8));
    int c0 = (int)(idx % (KPAD / 8)) * 8;
    const float* px = x + (size_t)r * KDIM;
    unsigned u[4];
#pragma unroll
    for (int q = 0; q < 4; q++) {
        int c = c0 + 2 * q;
        float f0 = (c < KDIM) ? __ldg(px + c) : 0.f;
        float f1 = (c + 1 < KDIM) ? __ldg(px + c + 1) : 0.f;
        u[q] = packbf(f0, f1);
    }
    *(uint4*)&d_xb[(size_t)r * KPAD + c0] = make_uint4(u[0], u[1], u[2], u[3]);
}

// W fp32 -> bf16.
__global__ void k_wprep(const float* __restrict__ W) {
    int i = blockIdx.x * 256 + threadIdx.x;          // float4 groups
    if (i * 4 < KDIM * HC) {
        float4 v = ((const float4*)W)[i];
        *(uint2*)&d_Wb[i * 4] = make_uint2(packbf(v.x, v.y), packbf(v.z, v.w));
    }
}

// Degree histogram. d_deg is 0 at rest (reset by k_scan1); self loop added in scan.
__global__ void k_deg(const void* __restrict__ ei) {
    int e = blockIdx.x * blockDim.x + threadIdx.x;
    if (e >= EE) return;
    int d;
    if (d_flag32) d = ((const int*)ei)[EE + e];
    else          d = (int)((const long long*)ei)[EE + e];
    atomicAdd(&d_deg[d], 1);
}

// Tensor-core GEMM: xp = x @ W via bf16 mma.m16n8k16 + ldmatrix.
// BOTH operands staged by cp.async 16B from pre-converted bf16 arrays:
// mainloop is pure ldsm + mma. Attention dots fused in the epilogue.
// Block tile 64x256, 8 warps (2M x 4N), warp tile 32x64.
__global__ void __launch_bounds__(256) k_gemm_tc(const float* __restrict__ att_s,
                                                 const float* __restrict__ att_d) {
    __shared__ __align__(16) __nv_bfloat16 As[2][BM][BK + 8];   // row 80B
    __shared__ __align__(16) __nv_bfloat16 Bs[2][BK][BN + 8];   // row 528B
    __shared__ float sAtt[2][HC];
    const int tid = threadIdx.x;
    const int lane = tid & 31, wid = tid >> 5;
    const int wm = (wid & 1) * 32;
    const int wn = (wid >> 1) * 64;
    const int hd = wid >> 1;                       // head of this warp's col slice
    const int gid = lane >> 2, tig = lane & 3;
    const int row0 = blockIdx.x * BM;

    sAtt[0][tid] = att_s[tid];
    sAtt[1][tid] = att_d[tid];

    // A staging: thread t covers row t>>2, 16B chunk t&3 (8 bf16 of k).
    const int arow = tid >> 2, aq = tid & 3;
    const int agr = row0 + arow;
    const bool aok = (agr < NN);
    const __nv_bfloat16* axp = d_xb + (size_t)(aok ? agr : 0) * KPAD + 8 * aq;

    float4 acc[2][8];
#pragma unroll
    for (int i = 0; i < 2; i++)
#pragma unroll
        for (int j = 0; j < 8; j++) acc[i][j] = make_float4(0.f, 0.f, 0.f, 0.f);

#define LDCPA(st, k0)                                                           \
    {                                                                           \
        unsigned da = (unsigned)__cvta_generic_to_shared(&As[st][arow][8 * aq]); \
        cpa16(da, axp + (k0), aok);                                             \
        _Pragma("unroll")                                                       \
        for (int q = 0; q < 4; q++) {                                           \
            int c = tid + 256 * q;                                              \
            int brow = c >> 5, bcol = (c & 31) * 8;                             \
            int gk = (k0) + brow;                                               \
            bool p = (gk < KDIM);                                               \
            unsigned db = (unsigned)__cvta_generic_to_shared(&Bs[st][brow][bcol]); \
            cpa16(db, d_Wb + (size_t)(p ? gk : 0) * HC + bcol, p);              \
        }                                                                       \
        asm volatile("cp.async.commit_group;\n");                               \
    }

    LDCPA(0, 0)
    asm volatile("cp.async.wait_group 0;\n");
    __syncthreads();

    for (int it = 0; it < NIT; it++) {
        const int s = it & 1;
        if (it + 1 < NIT) LDCPA(s ^ 1, (it + 1) * BK)

#pragma unroll
        for (int kk = 0; kk < BK; kk += 16) {
            unsigned a[2][4], bq[4][4];
#pragma unroll
            for (int i = 0; i < 2; i++) {
                unsigned ad = (unsigned)__cvta_generic_to_shared(
                    &As[s][wm + i * 16 + (lane & 15)][kk + (lane >> 4) * 8]);
                ldsm_x4(a[i][0], a[i][1], a[i][2], a[i][3], ad);
            }
#pragma unroll
            for (int j = 0; j < 4; j++) {
                unsigned ad = (unsigned)__cvta_generic_to_shared(
                    &Bs[s][kk + (lane & 15)][wn + j * 16 + (lane >> 4) * 8]);
                ldsm_x4t(bq[j][0], bq[j][1], bq[j][2], bq[j][3], ad);
            }
#pragma unroll
            for (int i = 0; i < 2; i++)
#pragma unroll
                for (int j = 0; j < 4; j++) {
                    mma_bf16(acc[i][2 * j], a[i][0], a[i][1], a[i][2], a[i][3],
                             bq[j][0], bq[j][1]);
                    mma_bf16(acc[i][2 * j + 1], a[i][0], a[i][1], a[i][2], a[i][3],
                             bq[j][2], bq[j][3]);
                }
        }

        if (it + 1 < NIT) {
            asm volatile("cp.async.wait_group 0;\n");
            __syncthreads();
        }
    }
#undef LDCPA

    // Epilogue: bf16x2 stores + fused attention dots (fp32 accumulators).
    float psA[2] = {0.f, 0.f}, pdA[2] = {0.f, 0.f};
    float psB[2] = {0.f, 0.f}, pdB[2] = {0.f, 0.f};
#pragma unroll
    for (int i = 0; i < 2; i++) {
        int r0 = row0 + wm + i * 16 + gid;
#pragma unroll
        for (int j = 0; j < 8; j++) {
            int c = wn + j * 8 + tig * 2;
            float avs0 = sAtt[0][c], avs1 = sAtt[0][c + 1];
            float avd0 = sAtt[1][c], avd1 = sAtt[1][c + 1];
            psA[i] += acc[i][j].x * avs0 + acc[i][j].y * avs1;
            pdA[i] += acc[i][j].x * avd0 + acc[i][j].y * avd1;
            psB[i] += acc[i][j].z * avs0 + acc[i][j].w * avs1;
            pdB[i] += acc[i][j].z * avd0 + acc[i][j].w * avd1;
            if (r0 < NN)
                d_xpb[((size_t)r0 * HC + c) >> 1] =
                    __float22bfloat162_rn(make_float2(acc[i][j].x, acc[i][j].y));
            if (r0 + 8 < NN)
                d_xpb[((size_t)(r0 + 8) * HC + c) >> 1] =
                    __float22bfloat162_rn(make_float2(acc[i][j].z, acc[i][j].w));
        }
    }
#pragma unroll
    for (int i = 0; i < 2; i++) {
        psA[i] += __shfl_xor_sync(0xffffffffu, psA[i], 1);
        psA[i] += __shfl_xor_sync(0xffffffffu, psA[i], 2);
        pdA[i] += __shfl_xor_sync(0xffffffffu, pdA[i], 1);
        pdA[i] += __shfl_xor_sync(0xffffffffu, pdA[i], 2);
        psB[i] += __shfl_xor_sync(0xffffffffu, psB[i], 1);
        psB[i] += __shfl_xor_sync(0xffffffffu, psB[i], 2);
        pdB[i] += __shfl_xor_sync(0xffffffffu, pdB[i], 1);
        pdB[i] += __shfl_xor_sync(0xffffffffu, pdB[i], 2);
        if (tig == 0) {
            int r0 = row0 + wm + i * 16 + gid;
            if (r0 < NN) {
                ((float*)&d_asrc[r0])[hd] = psA[i];
                ((float*)&d_adst[r0])[hd] = pdA[i];
            }
            if (r0 + 8 < NN) {
                ((float*)&d_asrc[r0 + 8])[hd] = psB[i];
                ((float*)&d_adst[r0 + 8])[hd] = pdB[i];
            }
        }
    }
}

// Exclusive scan of (deg+1) -> rowptr (3-phase); resets d_deg for next run.
__global__ void __launch_bounds__(1024) k_scan1() {
    __shared__ int sh[1024];
    int i = blockIdx.x * 1024 + threadIdx.x;
    int v = 0;
    if (i < NN) {
        v = d_deg[i] + 1;          // +1 = self loop
        d_deg[i] = 0;              // consumer-reset
    }
    sh[threadIdx.x] = v;
    __syncthreads();
    for (int off = 1; off < 1024; off <<= 1) {
        int t = 0;
        if (threadIdx.x >= off) t = sh[threadIdx.x - off];
        __syncthreads();
        sh[threadIdx.x] += t;
        __syncthreads();
    }
    if (i < NN) d_rowptr[i] = sh[threadIdx.x] - v;
    if (threadIdx.x == 1023) d_bsum[blockIdx.x] = sh[1023];
}
__global__ void k_scan2(int nblk) {
    if (threadIdx.x == 0 && blockIdx.x == 0) {
        int run = 0;
        for (int b = 0; b < nblk; b++) { d_boff[b] = run; run += d_bsum[b]; }
    }
}
__global__ void k_scan3() {
    int i = blockIdx.x * blockDim.x + threadIdx.x;
    if (i < NN) d_rowptr[i] += d_boff[i >> 10];
    if (i == 0) d_rowptr[NN] = ENQ;
}

// Edge scatter: pure index pass. Slot from atomicAdd on d_rowptr[d] itself
// (post-pass rowptr[n] == original rowptr[n+1]; k_agg reads [n-1],[n]).
// All float work (logit/exp) deferred to k_agg.
__global__ void k_edge(const void* __restrict__ ei) {
    int e = blockIdx.x * blockDim.x + threadIdx.x;
    if (e >= ENQ) return;
    int s, d;
    if (e < EE) { int2 sd = edge_sd(ei, e); s = sd.x; d = sd.y; }
    else { s = d = e - EE; }
    int slot = atomicAdd(&d_rowptr[d], 1);
    d_slot[slot] = s;
}

// Per-node aggregation: ONE WARP per node; lane owns a bf16x2 column pair per
// head. a_dst loaded once per node; per edge: 4B slot + 16B a_src (L2, uniform)
// + 4x64B coalesced xp gathers. ex computed in-loop (fp32, softmax-equivalent;
// segment-max skipped: logits O(1), exp cannot overflow).
__global__ void __launch_bounds__(256) k_agg(const void* __restrict__ batch,
                                             const float* __restrict__ bias) {
    int n = blockIdx.x * 8 + (threadIdx.x >> 5);
    int lane = threadIdx.x & 31;
    if (n >= NN) return;
    int beg = (n == 0) ? 0 : d_rowptr[n - 1];
    int end = d_rowptr[n];
    float4 ad = d_adst[n];
    float2 a0 = {0.f, 0.f}, a1 = {0.f, 0.f}, a2 = {0.f, 0.f}, a3 = {0.f, 0.f};
    float dn0 = 0.f, dn1 = 0.f, dn2 = 0.f, dn3 = 0.f;
    int i = beg;
    for (; i + 2 <= end; i += 2) {
        int sA = d_slot[i];
        int sB = d_slot[i + 1];
        const __nv_bfloat162* xrA = &d_xpb[(size_t)sA * HC / 2];
        const __nv_bfloat162* xrB = &d_xpb[(size_t)sB * HC / 2];
        float2 uA0 = bf2f(xrA[lane]),      uB0 = bf2f(xrB[lane]);
        float2 uA1 = bf2f(xrA[32 + lane]), uB1 = bf2f(xrB[32 + lane]);
        float2 uA2 = bf2f(xrA[64 + lane]), uB2 = bf2f(xrB[64 + lane]);
        float2 uA3 = bf2f(xrA[96 + lane]), uB3 = bf2f(xrB[96 + lane]);
        float4 asA = d_asrc[sA];
        float4 asB = d_asrc[sB];
        float eA0 = __expf(lrelu(asA.x + ad.x));
        float eA1 = __expf(lrelu(asA.y + ad.y));
        float eA2 = __expf(lrelu(asA.z + ad.z));
        float eA3 = __expf(lrelu(asA.w + ad.w));
        float eB0 = __expf(lrelu(asB.x + ad.x));
        float eB1 = __expf(lrelu(asB.y + ad.y));
        float eB2 = __expf(lrelu(asB.z + ad.z));
        float eB3 = __expf(lrelu(asB.w + ad.w));
        dn0 += eA0 + eB0; dn1 += eA1 + eB1;
        dn2 += eA2 + eB2; dn3 += eA3 + eB3;
        a0.x += eA0 * uA0.x + eB0 * uB0.x; a0.y += eA0 * uA0.y + eB0 * uB0.y;
        a1.x += eA1 * uA1.x + eB1 * uB1.x; a1.y += eA1 * uA1.y + eB1 * uB1.y;
        a2.x += eA2 * uA2.x + eB2 * uB2.x; a2.y += eA2 * uA2.y + eB2 * uB2.y;
        a3.x += eA3 * uA3.x + eB3 * uB3.x; a3.y += eA3 * uA3.y + eB3 * uB3.y;
    }
    if (i < end) {
        int sA = d_slot[i];
        const __nv_bfloat162* xr = &d_xpb[(size_t)sA * HC / 2];
        float2 v0 = bf2f(xr[lane]);
        float2 v1 = bf2f(xr[32 + lane]);
        float2 v2 = bf2f(xr[64 + lane]);
        float2 v3 = bf2f(xr[96 + lane]);
        float4 asA = d_asrc[sA];
        float e0 = __expf(lrelu(asA.x + ad.x));
        float e1 = __expf(lrelu(asA.y + ad.y));
        float e2 = __expf(lrelu(asA.z + ad.z));
        float e3 = __expf(lrelu(asA.w + ad.w));
        dn0 += e0; dn1 += e1; dn2 += e2; dn3 += e3;
        a0.x += e0 * v0.x; a0.y += e0 * v0.y;
        a1.x += e1 * v1.x; a1.y += e1 * v1.y;
        a2.x += e2 * v2.x; a2.y += e2 * v2.y;
        a3.x += e3 * v3.x; a3.y += e3 * v3.y;
    }
    float2 bv = ((const float2*)bias)[lane];
    float hv0 = 0.25f * (a0.x / dn0 + a1.x / dn1 + a2.x / dn2 + a3.x / dn3) + bv.x;
    float hv1 = 0.25f * (a0.y / dn0 + a1.y / dn1 + a2.y / dn2 + a3.y / dn3) + bv.y;
    hv0 = fmaxf(hv0, 0.f);
    hv1 = fmaxf(hv1, 0.f);
    int g = batch_of(batch, n);
    atomicAdd(&d_gsum[g * 64 + 2 * lane], hv0);
    atomicAdd(&d_gsum[g * 64 + 2 * lane + 1], hv1);
    if (lane == 0) atomicAdd(&d_gcnt[g], 1);
}

// Head MLP: one block per graph. Also consumer-resets gsum/gcnt/flag32.
__global__ void k_mlp(const float* __restrict__ w1, const float* __restrict__ b1,
                      const float* __restrict__ w2, const float* __restrict__ b2,
                      float* __restrict__ out) {
    __shared__ float sg[64], sz[64];
    int g = blockIdx.x, c = threadIdx.x;
    float cnt = (float)d_gcnt[g];
    if (cnt < 1.f) cnt = 1.f;
    sg[c] = d_gsum[g * 64 + c] / cnt;
    __syncthreads();
    d_gsum[g * 64 + c] = 0.f;                 // consumer-reset
    if (c == 0) d_gcnt[g] = 0;
    if (g == 0 && c == 0) d_flag32 = 0;
    float z = b1[c];
#pragma unroll 16
    for (int k = 0; k < 64; k++) z += sg[k] * w1[k * 64 + c];
    z = fmaxf(z, 0.f);
    sz[c] = z * w2[c];
    __syncthreads();
    if (c < 32) {
        float v = sz[c] + sz[c + 32];
#pragma unroll
        for (int o = 16; o; o >>= 1) v += __shfl_down_sync(0xffffffffu, v, o);
        if (c == 0) out[g] = 1.f / (1.f + expf(-(v + b2[0])));
    }
}

// ---------------- launcher ----------------
extern "C" void kernel_launch(void* const* d_in, const int* in_sizes, int n_in,
                              void* d_out, int out_size) {
    const float* x     = (const float*)d_in[0];
    const float* W     = (const float*)d_in[1];
    const float* att_s = (const float*)d_in[2];
    const float* att_d = (const float*)d_in[3];
    const float* bias  = (const float*)d_in[4];
    const float* w1    = (const float*)d_in[5];
    const float* b1    = (const float*)d_in[6];
    const float* w2    = (const float*)d_in[7];
    const float* b2    = (const float*)d_in[8];
    const void*  ei    = d_in[9];
    const void*  batch = d_in[10];
    float* out = (float*)d_out;

    k_detect<<<128, 256>>>((const unsigned*)ei);
    k_xprep<<<(int)(((long long)NN * (KPAD / 8) + 255) / 256), 256>>>(x);
    k_wprep<<<(KDIM * HC / 4 + 255) / 256, 256>>>(W);
    k_gemm_tc<<<(NN + BM - 1) / BM, 256>>>(att_s, att_d);      // profile slot 4
    k_deg<<<(EE + 255) / 256, 256>>>(ei);
    int scan_blks = (NN + 1023) / 1024;
    k_scan1<<<scan_blks, 1024>>>();
    k_scan2<<<1, 32>>>(scan_blks);
    k_scan3<<<(NN + 255) / 256, 256>>>();
    k_edge<<<(ENQ + 255) / 256, 256>>>(ei);
    k_agg<<<(NN + 7) / 8, 256>>>(batch, bias);
    k_mlp<<<GGR, 64>>>(w1, b1, w2, b2, out);
}

// round 11
// speedup vs baseline: 1.0255x; 1.0255x over previous
#include <cuda_runtime.h>
#include <cuda_bf16.h>

// Problem constants (fixed by the reference)
#define NN 100000
#define EE 1600000
#define ENQ 1700000        // EE + NN (edges + self loops)
#define GGR 128
#define KDIM 329
#define HC 256             // H*C = 4*64

// GEMM tiling: single pass over all 256 columns
#define BM 64
#define BN 256
#define BK 32
#define KPAD 352           // KDIM padded to NIT*BK (11*32), 16B-aligned rows
#define NIT (KPAD / BK)    // 11

// ---------------- static device scratch (no cudaMalloc allowed) ----------------
__device__ __nv_bfloat162 d_xpb[(size_t)NN * HC / 2]; // [N, H*C] projected feats, bf16
__device__ __nv_bfloat16  d_xb[(size_t)NN * KPAD];    // x in bf16, zero-padded cols
__device__ __nv_bfloat16  d_Wb[KDIM * HC];            // W in bf16 (k_wprep)
__device__ float4 d_asrc[NN];             // a_src[n][4]
__device__ float4 d_adst[NN];             // a_dst[n][4]
__device__ uint4  d_slot[ENQ];            // CSR slot: {src, ex01(bf16x2), ex23(bf16x2), 0}
__device__ int    d_deg[NN];              // zero at rest; reset by k_scan1
__device__ int    d_rowptr[NN + 1];       // rebuilt every run by scans
__device__ int    d_bsum[128];
__device__ int    d_boff[128];
__device__ float  d_gsum[GGR * 64];       // zero at rest; reset by k_mlp
__device__ int    d_gcnt[GGR];            // zero at rest; reset by k_mlp
__device__ int    d_flag32;               // 1 if int32 inputs; reset by k_mlp

// ---------------- helpers ----------------
__device__ __forceinline__ int2 edge_sd(const void* ei, int e) {
    if (d_flag32) {
        const int* p = (const int*)ei;
        return make_int2(p[e], p[EE + e]);
    } else {
        const long long* p = (const long long*)ei;
        return make_int2((int)p[e], (int)p[EE + e]);
    }
}
__device__ __forceinline__ int batch_of(const void* b, int n) {
    if (d_flag32) return ((const int*)b)[n];
    return (int)((const long long*)b)[n];
}
__device__ __forceinline__ float lrelu(float v) { return v > 0.f ? v : 0.2f * v; }
__device__ __forceinline__ float2 bf2f(__nv_bfloat162 v) { return __bfloat1622float2(v); }
__device__ __forceinline__ unsigned packbf(float a, float b) {
    __nv_bfloat162 p = __float22bfloat162_rn(make_float2(a, b));
    return *(unsigned*)&p;
}
__device__ __forceinline__ void cpa16(unsigned dst, const void* src, bool p) {
    int sz = p ? 16 : 0;
    asm volatile("cp.async.cg.shared.global [%0], [%1], 16, %2;\n"
                 :: "r"(dst), "l"(src), "r"(sz));
}
__device__ __forceinline__ void ldsm_x4(unsigned& r0, unsigned& r1, unsigned& r2, unsigned& r3,
                                        unsigned addr) {
    asm volatile("ldmatrix.sync.aligned.m8n8.x4.shared.b16 {%0,%1,%2,%3}, [%4];"
                 : "=r"(r0), "=r"(r1), "=r"(r2), "=r"(r3) : "r"(addr));
}
__device__ __forceinline__ void ldsm_x4t(unsigned& r0, unsigned& r1, unsigned& r2, unsigned& r3,
                                         unsigned addr) {
    asm volatile("ldmatrix.sync.aligned.m8n8.x4.trans.shared.b16 {%0,%1,%2,%3}, [%4];"
                 : "=r"(r0), "=r"(r1), "=r"(r2), "=r"(r3) : "r"(addr));
}
__device__ __forceinline__ void mma_bf16(float4& d,
                                         unsigned a0, unsigned a1, unsigned a2, unsigned a3,
                                         unsigned b0, unsigned b1) {
    asm volatile(
        "mma.sync.aligned.m16n8k16.row.col.f32.bf16.bf16.f32 "
        "{%0,%1,%2,%3}, {%4,%5,%6,%7}, {%8,%9}, {%0,%1,%2,%3};\n"
        : "+f"(d.x), "+f"(d.y), "+f"(d.z), "+f"(d.w)
        : "r"(a0), "r"(a1), "r"(a2), "r"(a3), "r"(b0), "r"(b1));
}

// ---------------- kernels ----------------
// Detect int32 vs int64: in an int64 LE array the odd 32-bit words (hi) are all 0.
// d_flag32 is 0 at rest (reset by k_mlp at the end of every run).
__global__ void k_detect(const unsigned* __restrict__ ei) {
    int i = blockIdx.x * blockDim.x + threadIdx.x;
    bool nz = false;
    for (int e = i; e < EE; e += gridDim.x * blockDim.x)
        nz |= (ei[2 * e + 1] != 0u);
    unsigned b = __ballot_sync(0xffffffffu, nz);
    if ((threadIdx.x & 31) == 0 && b) atomicOr(&d_flag32, 1);
}

// x fp32 -> bf16, padded to KPAD cols. One 16B chunk (8 cols) per thread.
__global__ void k_xprep(const float* __restrict__ x) {
    long long idx = (long long)blockIdx.x * 256 + threadIdx.x;
    if (idx >= (long long)NN * (KPAD / 8)) return;
    int r = (int)(idx / (KPAD / 8));
    int c0 = (int)(idx % (KPAD / 8)) * 8;
    const float* px = x + (size_t)r * KDIM;
    unsigned u[4];
#pragma unroll
    for (int q = 0; q < 4; q++) {
        int c = c0 + 2 * q;
        float f0 = (c < KDIM) ? __ldg(px + c) : 0.f;
        float f1 = (c + 1 < KDIM) ? __ldg(px + c + 1) : 0.f;
        u[q] = packbf(f0, f1);
    }
    *(uint4*)&d_xb[(size_t)r * KPAD + c0] = make_uint4(u[0], u[1], u[2], u[3]);
}

// W fp32 -> bf16.
__global__ void k_wprep(const float* __restrict__ W) {
    int i = blockIdx.x * 256 + threadIdx.x;          // float4 groups
    if (i * 4 < KDIM * HC) {
        float4 v = ((const float4*)W)[i];
        *(uint2*)&d_Wb[i * 4] = make_uint2(packbf(v.x, v.y), packbf(v.z, v.w));
    }
}

// Degree histogram. d_deg is 0 at rest (reset by k_scan1); self loop added in scan.
__global__ void k_deg(const void* __restrict__ ei) {
    int e = blockIdx.x * blockDim.x + threadIdx.x;
    if (e >= EE) return;
    int d;
    if (d_flag32) d = ((const int*)ei)[EE + e];
    else          d = (int)((const long long*)ei)[EE + e];
    atomicAdd(&d_deg[d], 1);
}

// Tensor-core GEMM: xp = x @ W via bf16 mma.m16n8k16 + ldmatrix.
// BOTH operands staged by cp.async 16B from pre-converted bf16 arrays:
// mainloop is pure ldsm + mma. Attention dots fused in the epilogue.
// Block tile 64x256, 8 warps (2M x 4N), warp tile 32x64.
__global__ void __launch_bounds__(256) k_gemm_tc(const float* __restrict__ att_s,
                                                 const float* __restrict__ att_d) {
    __shared__ __align__(16) __nv_bfloat16 As[2][BM][BK + 8];   // row 80B
    __shared__ __align__(16) __nv_bfloat16 Bs[2][BK][BN + 8];   // row 528B
    __shared__ float sAtt[2][HC];
    const int tid = threadIdx.x;
    const int lane = tid & 31, wid = tid >> 5;
    const int wm = (wid & 1) * 32;
    const int wn = (wid >> 1) * 64;
    const int hd = wid >> 1;                       // head of this warp's col slice
    const int gid = lane >> 2, tig = lane & 3;
    const int row0 = blockIdx.x * BM;

    sAtt[0][tid] = att_s[tid];
    sAtt[1][tid] = att_d[tid];

    // A staging: thread t covers row t>>2, 16B chunk t&3 (8 bf16 of k).
    const int arow = tid >> 2, aq = tid & 3;
    const int agr = row0 + arow;
    const bool aok = (agr < NN);
    const __nv_bfloat16* axp = d_xb + (size_t)(aok ? agr : 0) * KPAD + 8 * aq;

    float4 acc[2][8];
#pragma unroll
    for (int i = 0; i < 2; i++)
#pragma unroll
        for (int j = 0; j < 8; j++) acc[i][j] = make_float4(0.f, 0.f, 0.f, 0.f);

#define LDCPA(st, k0)                                                           \
    {                                                                           \
        unsigned da = (unsigned)__cvta_generic_to_shared(&As[st][arow][8 * aq]); \
        cpa16(da, axp + (k0), aok);                                             \
        _Pragma("unroll")                                                       \
        for (int q = 0; q < 4; q++) {                                           \
            int c = tid + 256 * q;                                              \
            int brow = c >> 5, bcol = (c & 31) * 8;                             \
            int gk = (k0) + brow;                                               \
            bool p = (gk < KDIM);                                               \
            unsigned db = (unsigned)__cvta_generic_to_shared(&Bs[st][brow][bcol]); \
            cpa16(db, d_Wb + (size_t)(p ? gk : 0) * HC + bcol, p);              \
        }                                                                       \
        asm volatile("cp.async.commit_group;\n");                               \
    }

    LDCPA(0, 0)
    asm volatile("cp.async.wait_group 0;\n");
    __syncthreads();

    for (int it = 0; it < NIT; it++) {
        const int s = it & 1;
        if (it + 1 < NIT) LDCPA(s ^ 1, (it + 1) * BK)

#pragma unroll
        for (int kk = 0; kk < BK; kk += 16) {
            unsigned a[2][4], bq[4][4];
#pragma unroll
            for (int i = 0; i < 2; i++) {
                unsigned ad = (unsigned)__cvta_generic_to_shared(
                    &As[s][wm + i * 16 + (lane & 15)][kk + (lane >> 4) * 8]);
                ldsm_x4(a[i][0], a[i][1], a[i][2], a[i][3], ad);
            }
#pragma unroll
            for (int j = 0; j < 4; j++) {
                unsigned ad = (unsigned)__cvta_generic_to_shared(
                    &Bs[s][kk + (lane & 15)][wn + j * 16 + (lane >> 4) * 8]);
                ldsm_x4t(bq[j][0], bq[j][1], bq[j][2], bq[j][3], ad);
            }
#pragma unroll
            for (int i = 0; i < 2; i++)
#pragma unroll
                for (int j = 0; j < 4; j++) {
                    mma_bf16(acc[i][2 * j], a[i][0], a[i][1], a[i][2], a[i][3],
                             bq[j][0], bq[j][1]);
                    mma_bf16(acc[i][2 * j + 1], a[i][0], a[i][1], a[i][2], a[i][3],
                             bq[j][2], bq[j][3]);
                }
        }

        if (it + 1 < NIT) {
            asm volatile("cp.async.wait_group 0;\n");
            __syncthreads();
        }
    }
#undef LDCPA

    // Epilogue: bf16x2 stores + fused attention dots (fp32 accumulators).
    float psA[2] = {0.f, 0.f}, pdA[2] = {0.f, 0.f};
    float psB[2] = {0.f, 0.f}, pdB[2] = {0.f, 0.f};
#pragma unroll
    for (int i = 0; i < 2; i++) {
        int r0 = row0 + wm + i * 16 + gid;
#pragma unroll
        for (int j = 0; j < 8; j++) {
            int c = wn + j * 8 + tig * 2;
            float avs0 = sAtt[0][c], avs1 = sAtt[0][c + 1];
            float avd0 = sAtt[1][c], avd1 = sAtt[1][c + 1];
            psA[i] += acc[i][j].x * avs0 + acc[i][j].y * avs1;
            pdA[i] += acc[i][j].x * avd0 + acc[i][j].y * avd1;
            psB[i] += acc[i][j].z * avs0 + acc[i][j].w * avs1;
            pdB[i] += acc[i][j].z * avd0 + acc[i][j].w * avd1;
            if (r0 < NN)
                d_xpb[((size_t)r0 * HC + c) >> 1] =
                    __float22bfloat162_rn(make_float2(acc[i][j].x, acc[i][j].y));
            if (r0 + 8 < NN)
                d_xpb[((size_t)(r0 + 8) * HC + c) >> 1] =
                    __float22bfloat162_rn(make_float2(acc[i][j].z, acc[i][j].w));
        }
    }
#pragma unroll
    for (int i = 0; i < 2; i++) {
        psA[i] += __shfl_xor_sync(0xffffffffu, psA[i], 1);
        psA[i] += __shfl_xor_sync(0xffffffffu, psA[i], 2);
        pdA[i] += __shfl_xor_sync(0xffffffffu, pdA[i], 1);
        pdA[i] += __shfl_xor_sync(0xffffffffu, pdA[i], 2);
        psB[i] += __shfl_xor_sync(0xffffffffu, psB[i], 1);
        psB[i] += __shfl_xor_sync(0xffffffffu, psB[i], 2);
        pdB[i] += __shfl_xor_sync(0xffffffffu, pdB[i], 1);
        pdB[i] += __shfl_xor_sync(0xffffffffu, pdB[i], 2);
        if (tig == 0) {
            int r0 = row0 + wm + i * 16 + gid;
            if (r0 < NN) {
                ((float*)&d_asrc[r0])[hd] = psA[i];
                ((float*)&d_adst[r0])[hd] = pdA[i];
            }
            if (r0 + 8 < NN) {
                ((float*)&d_asrc[r0 + 8])[hd] = psB[i];
                ((float*)&d_adst[r0 + 8])[hd] = pdB[i];
            }
        }
    }
}

// Exclusive scan of (deg+1) -> rowptr (3-phase); resets d_deg for next run.
__global__ void __launch_bounds__(1024) k_scan1() {
    __shared__ int sh[1024];
    int i = blockIdx.x * 1024 + threadIdx.x;
    int v = 0;
    if (i < NN) {
        v = d_deg[i] + 1;          // +1 = self loop
        d_deg[i] = 0;              // consumer-reset
    }
    sh[threadIdx.x] = v;
    __syncthreads();
    for (int off = 1; off < 1024; off <<= 1) {
        int t = 0;
        if (threadIdx.x >= off) t = sh[threadIdx.x - off];
        __syncthreads();
        sh[threadIdx.x] += t;
        __syncthreads();
    }
    if (i < NN) d_rowptr[i] = sh[threadIdx.x] - v;
    if (threadIdx.x == 1023) d_bsum[blockIdx.x] = sh[1023];
}
__global__ void k_scan2(int nblk) {
    if (threadIdx.x == 0 && blockIdx.x == 0) {
        int run = 0;
        for (int b = 0; b < nblk; b++) { d_boff[b] = run; run += d_bsum[b]; }
    }
}
__global__ void k_scan3() {
    int i = blockIdx.x * blockDim.x + threadIdx.x;
    if (i < NN) d_rowptr[i] += d_boff[i >> 10];
    if (i == 0) d_rowptr[NN] = ENQ;
}

// Single edge pass: ex = exp(leaky(logit)); scatter packed {src, ex(bf16x4)}
// with ONE 16B store and ONE atomic (on d_rowptr[d] itself; post-pass
// rowptr[n] == original rowptr[n+1], k_agg reads [n-1],[n]).
// (segment-max skipped: logits O(1), exp cannot overflow; softmax identical.)
__global__ void k_edge(const void* __restrict__ ei) {
    int e = blockIdx.x * blockDim.x + threadIdx.x;
    if (e >= ENQ) return;
    int s, d;
    if (e < EE) { int2 sd = edge_sd(ei, e); s = sd.x; d = sd.y; }
    else { s = d = e - EE; }
    float4 as = d_asrc[s], ad = d_adst[d];
    float ex0 = __expf(lrelu(as.x + ad.x));
    float ex1 = __expf(lrelu(as.y + ad.y));
    float ex2 = __expf(lrelu(as.z + ad.z));
    float ex3 = __expf(lrelu(as.w + ad.w));
    int slot = atomicAdd(&d_rowptr[d], 1);
    uint4 sl;
    sl.x = (unsigned)s;
    sl.y = packbf(ex0, ex1);
    sl.z = packbf(ex2, ex3);
    sl.w = 0u;
    d_slot[slot] = sl;
}

// Per-node aggregation: ONE WARP per node; lane owns bf16x2 column pair per
// head. Slot loads warp-uniform; xp gathers coalesced 128B per head.
// 2-way unroll for MLP. Local denominator; divide once at the end.
__global__ void __launch_bounds__(256) k_agg(const void* __restrict__ batch,
                                             const float* __restrict__ bias) {
    int n = blockIdx.x * 8 + (threadIdx.x >> 5);
    int lane = threadIdx.x & 31;
    if (n >= NN) return;
    int beg = (n == 0) ? 0 : d_rowptr[n - 1];
    int end = d_rowptr[n];
    float2 a0 = {0.f, 0.f}, a1 = {0.f, 0.f}, a2 = {0.f, 0.f}, a3 = {0.f, 0.f};
    float dn0 = 0.f, dn1 = 0.f, dn2 = 0.f, dn3 = 0.f;
    int i = beg;
    for (; i + 2 <= end; i += 2) {
        uint4 slA = d_slot[i];
        uint4 slB = d_slot[i + 1];
        const __nv_bfloat162* xrA = &d_xpb[(size_t)(int)slA.x * HC / 2];
        const __nv_bfloat162* xrB = &d_xpb[(size_t)(int)slB.x * HC / 2];
        float2 uA0 = bf2f(xrA[lane]),      uB0 = bf2f(xrB[lane]);
        float2 uA1 = bf2f(xrA[32 + lane]), uB1 = bf2f(xrB[32 + lane]);
        float2 uA2 = bf2f(xrA[64 + lane]), uB2 = bf2f(xrB[64 + lane]);
        float2 uA3 = bf2f(xrA[96 + lane]), uB3 = bf2f(xrB[96 + lane]);
        float2 eA01 = bf2f(*(__nv_bfloat162*)&slA.y);
        float2 eA23 = bf2f(*(__nv_bfloat162*)&slA.z);
        float2 eB01 = bf2f(*(__nv_bfloat162*)&slB.y);
        float2 eB23 = bf2f(*(__nv_bfloat162*)&slB.z);
        dn0 += eA01.x + eB01.x; dn1 += eA01.y + eB01.y;
        dn2 += eA23.x + eB23.x; dn3 += eA23.y + eB23.y;
        a0.x += eA01.x * uA0.x + eB01.x * uB0.x; a0.y += eA01.x * uA0.y + eB01.x * uB0.y;
        a1.x += eA01.y * uA1.x + eB01.y * uB1.x; a1.y += eA01.y * uA1.y + eB01.y * uB1.y;
        a2.x += eA23.x * uA2.x + eB23.x * uB2.x; a2.y += eA23.x * uA2.y + eB23.x * uB2.y;
        a3.x += eA23.y * uA3.x + eB23.y * uB3.x; a3.y += eA23.y * uA3.y + eB23.y * uB3.y;
    }
    if (i < end) {
        uint4 sl = d_slot[i];
        const __nv_bfloat162* xr = &d_xpb[(size_t)(int)sl.x * HC / 2];
        float2 al01 = bf2f(*(__nv_bfloat162*)&sl.y);
        float2 al23 = bf2f(*(__nv_bfloat162*)&sl.z);
        dn0 += al01.x; dn1 += al01.y; dn2 += al23.x; dn3 += al23.y;
        float2 v0 = bf2f(xr[lane]);
        float2 v1 = bf2f(xr[32 + lane]);
        float2 v2 = bf2f(xr[64 + lane]);
        float2 v3 = bf2f(xr[96 + lane]);
        a0.x += al01.x * v0.x; a0.y += al01.x * v0.y;
        a1.x += al01.y * v1.x; a1.y += al01.y * v1.y;
        a2.x += al23.x * v2.x; a2.y += al23.x * v2.y;
        a3.x += al23.y * v3.x; a3.y += al23.y * v3.y;
    }
    float2 bv = ((const float2*)bias)[lane];
    float hv0 = 0.25f * (a0.x / dn0 + a1.x / dn1 + a2.x / dn2 + a3.x / dn3) + bv.x;
    float hv1 = 0.25f * (a0.y / dn0 + a1.y / dn1 + a2.y / dn2 + a3.y / dn3) + bv.y;
    hv0 = fmaxf(hv0, 0.f);
    hv1 = fmaxf(hv1, 0.f);
    int g = batch_of(batch, n);
    atomicAdd(&d_gsum[g * 64 + 2 * lane], hv0);
    atomicAdd(&d_gsum[g * 64 + 2 * lane + 1], hv1);
    if (lane == 0) atomicAdd(&d_gcnt[g], 1);
}

// Head MLP: one block per graph. Also consumer-resets gsum/gcnt/flag32.
__global__ void k_mlp(const float* __restrict__ w1, const float* __restrict__ b1,
                      const float* __restrict__ w2, const float* __restrict__ b2,
                      float* __restrict__ out) {
    __shared__ float sg[64], sz[64];
    int g = blockIdx.x, c = threadIdx.x;
    float cnt = (float)d_gcnt[g];
    if (cnt < 1.f) cnt = 1.f;
    sg[c] = d_gsum[g * 64 + c] / cnt;
    __syncthreads();
    d_gsum[g * 64 + c] = 0.f;                 // consumer-reset
    if (c == 0) d_gcnt[g] = 0;
    if (g == 0 && c == 0) d_flag32 = 0;
    float z = b1[c];
#pragma unroll 16
    for (int k = 0; k < 64; k++) z += sg[k] * w1[k * 64 + c];
    z = fmaxf(z, 0.f);
    sz[c] = z * w2[c];
    __syncthreads();
    if (c < 32) {
        float v = sz[c] + sz[c + 32];
#pragma unroll
        for (int o = 16; o; o >>= 1) v += __shfl_down_sync(0xffffffffu, v, o);
        if (c == 0) out[g] = 1.f / (1.f + expf(-(v + b2[0])));
    }
}

// ---------------- launcher ----------------
extern "C" void kernel_launch(void* const* d_in, const int* in_sizes, int n_in,
                              void* d_out, int out_size) {
    const float* x     = (const float*)d_in[0];
    const float* W     = (const float*)d_in[1];
    const float* att_s = (const float*)d_in[2];
    const float* att_d = (const float*)d_in[3];
    const float* bias  = (const float*)d_in[4];
    const float* w1    = (const float*)d_in[5];
    const float* b1    = (const float*)d_in[6];
    const float* w2    = (const float*)d_in[7];
    const float* b2    = (const float*)d_in[8];
    const void*  ei    = d_in[9];
    const void*  batch = d_in[10];
    float* out = (float*)d_out;

    k_detect<<<128, 256>>>((const unsigned*)ei);
    k_xprep<<<(int)(((long long)NN * (KPAD / 8) + 255) / 256), 256>>>(x);
    k_wprep<<<(KDIM * HC / 4 + 255) / 256, 256>>>(W);
    k_gemm_tc<<<(NN + BM - 1) / BM, 256>>>(att_s, att_d);      // profile slot 4
    k_deg<<<(EE + 255) / 256, 256>>>(ei);
    int scan_blks = (NN + 1023) / 1024;
    k_scan1<<<scan_blks, 1024>>>();
    k_scan2<<<1, 32>>>(scan_blks);
    k_scan3<<<(NN + 255) / 256, 256>>>();
    k_edge<<<(ENQ + 255) / 256, 256>>>(ei);
    k_agg<<<(NN + 7) / 8, 256>>>(batch, bias);
    k_mlp<<<GGR, 64>>>(w1, b1, w2, b2, out);
}

// round 12
// speedup vs baseline: 1.0613x; 1.0349x over previous
#include <cuda_runtime.h>
#include <cuda_bf16.h>

// Problem constants (fixed by the reference)
#define NN 100000
#define EE 1600000
#define ENQ 1700000        // EE + NN (edges + self loops)
#define GGR 128
#define KDIM 329
#define HC 256             // H*C = 4*64

// GEMM tiling: single pass over all 256 columns
#define BM 64
#define BN 256
#define BK 32
#define NIT ((KDIM + BK - 1) / BK)   // 11

// ---------------- static device scratch (no cudaMalloc allowed) ----------------
__device__ __nv_bfloat162 d_xpb[(size_t)NN * HC / 2]; // [N, H*C] projected feats, bf16
__device__ __nv_bfloat16  d_Wb[KDIM * HC];            // W in bf16 (k_wprep)
__device__ float4 d_asrc[NN];             // a_src[n][4]
__device__ float4 d_adst[NN];             // a_dst[n][4]
__device__ uint4  d_slot[ENQ];            // CSR slot: {src, ex01(bf16x2), ex23(bf16x2), 0}
__device__ int    d_deg[NN];              // zero at rest; reset by k_scan1
__device__ int    d_rowptr[NN + 1];       // rebuilt every run by scans
__device__ int    d_bsum[128];
__device__ float  d_gsum[GGR * 64];       // zero at rest; reset by k_mlp
__device__ int    d_gcnt[GGR];            // zero at rest; reset by k_mlp
__device__ int    d_flag32;               // 1 if int32 inputs; reset by k_mlp

// ---------------- helpers ----------------
__device__ __forceinline__ int batch_of(const void* b, int n) {
    if (d_flag32) return ((const int*)b)[n];
    return (int)((const long long*)b)[n];
}
__device__ __forceinline__ float lrelu(float v) { return v > 0.f ? v : 0.2f * v; }
__device__ __forceinline__ float2 bf2f(__nv_bfloat162 v) { return __bfloat1622float2(v); }
__device__ __forceinline__ unsigned packbf(float a, float b) {
    __nv_bfloat162 p = __float22bfloat162_rn(make_float2(a, b));
    return *(unsigned*)&p;
}
__device__ __forceinline__ void cpa16(unsigned dst, const void* src, bool p) {
    int sz = p ? 16 : 0;
    asm volatile("cp.async.cg.shared.global [%0], [%1], 16, %2;\n"
                 :: "r"(dst), "l"(src), "r"(sz));
}
__device__ __forceinline__ void ldsm_x4(unsigned& r0, unsigned& r1, unsigned& r2, unsigned& r3,
                                        unsigned addr) {
    asm volatile("ldmatrix.sync.aligned.m8n8.x4.shared.b16 {%0,%1,%2,%3}, [%4];"
                 : "=r"(r0), "=r"(r1), "=r"(r2), "=r"(r3) : "r"(addr));
}
__device__ __forceinline__ void ldsm_x4t(unsigned& r0, unsigned& r1, unsigned& r2, unsigned& r3,
                                         unsigned addr) {
    asm volatile("ldmatrix.sync.aligned.m8n8.x4.trans.shared.b16 {%0,%1,%2,%3}, [%4];"
                 : "=r"(r0), "=r"(r1), "=r"(r2), "=r"(r3) : "r"(addr));
}
__device__ __forceinline__ void mma_bf16(float4& d,
                                         unsigned a0, unsigned a1, unsigned a2, unsigned a3,
                                         unsigned b0, unsigned b1) {
    asm volatile(
        "mma.sync.aligned.m16n8k16.row.col.f32.bf16.bf16.f32 "
        "{%0,%1,%2,%3}, {%4,%5,%6,%7}, {%8,%9}, {%0,%1,%2,%3};\n"
        : "+f"(d.x), "+f"(d.y), "+f"(d.z), "+f"(d.w)
        : "r"(a0), "r"(a1), "r"(a2), "r"(a3), "r"(b0), "r"(b1));
}

// ---------------- kernels ----------------
// W fp32 -> bf16.
__global__ void k_wprep(const float* __restrict__ W) {
    int i = blockIdx.x * 256 + threadIdx.x;          // float4 groups
    if (i * 4 < KDIM * HC) {
        float4 v = ((const float4*)W)[i];
        *(uint2*)&d_Wb[i * 4] = make_uint2(packbf(v.x, v.y), packbf(v.z, v.w));
    }
}

// Detect int32 vs int64: in an int64 LE array the odd 32-bit words (hi) are all 0.
// d_flag32 is 0 at rest (reset by k_mlp at the end of every run).
__global__ void k_detect(const unsigned* __restrict__ ei) {
    int i = blockIdx.x * blockDim.x + threadIdx.x;
    bool nz = false;
    for (int e = i; e < EE; e += gridDim.x * blockDim.x)
        nz |= (ei[2 * e + 1] != 0u);
    unsigned b = __ballot_sync(0xffffffffu, nz);
    if ((threadIdx.x & 31) == 0 && b) atomicOr(&d_flag32, 1);
}

// Degree histogram, 2 edges/thread (EE even -> pairs aligned & in-bounds).
__global__ void k_deg(const void* __restrict__ ei) {
    int e = (blockIdx.x * blockDim.x + threadIdx.x) * 2;
    if (e >= EE) return;
    int d0, d1;
    if (d_flag32) {
        int2 dv = *(const int2*)((const int*)ei + EE + e);
        d0 = dv.x; d1 = dv.y;
    } else {
        longlong2 dv = *(const longlong2*)((const long long*)ei + EE + e);
        d0 = (int)dv.x; d1 = (int)dv.y;
    }
    atomicAdd(&d_deg[d0], 1);
    atomicAdd(&d_deg[d1], 1);
}

// Tensor-core GEMM: xp = x @ W via bf16 mma.m16n8k16 + ldmatrix.
// A: scalar LDG (x rows only 4B-aligned) -> pack -> STS.64.
// B: cp.async 16B direct from pre-converted d_Wb.
// Attention dots fused in the epilogue. Block 64x256, 8 warps (2M x 4N).
__global__ void __launch_bounds__(256) k_gemm_tc(const float* __restrict__ x,
                                                 const float* __restrict__ att_s,
                                                 const float* __restrict__ att_d) {
    __shared__ __align__(16) __nv_bfloat16 As[2][BM][BK + 8];   // row 80B
    __shared__ __align__(16) __nv_bfloat16 Bs[2][BK][BN + 8];   // row 528B
    __shared__ float sAtt[2][HC];
    const int tid = threadIdx.x;
    const int lane = tid & 31, wid = tid >> 5;
    const int wm = (wid & 1) * 32;
    const int wn = (wid >> 1) * 64;
    const int hd = wid >> 1;                       // head of this warp's col slice
    const int gid = lane >> 2, tig = lane & 3;
    const int row0 = blockIdx.x * BM;

    sAtt[0][tid] = att_s[tid];
    sAtt[1][tid] = att_d[tid];

    // A staging: lane g = tid&7 owns k in [4g, 4g+4); row rA = tid>>3 (+32 for h=1).
    const int g = tid & 7, rA = tid >> 3;
    bool rokh[2]; const float* pxh[2];
#pragma unroll
    for (int h = 0; h < 2; h++) {
        int gr = row0 + rA + 32 * h;
        rokh[h] = (gr < NN);
        pxh[h] = x + (size_t)(rokh[h] ? gr : 0) * KDIM;
    }

    float aF[2][4];
    float4 acc[2][8];
#pragma unroll
    for (int i = 0; i < 2; i++)
#pragma unroll
        for (int j = 0; j < 8; j++) acc[i][j] = make_float4(0.f, 0.f, 0.f, 0.f);

#define LDGA(k0)                                                                \
    {                                                                           \
        _Pragma("unroll")                                                       \
        for (int h = 0; h < 2; h++)                                             \
        _Pragma("unroll")                                                       \
        for (int q = 0; q < 4; q++) {                                           \
            int k = (k0) + 4 * g + q;                                           \
            aF[h][q] = (rokh[h] && k < KDIM) ? __ldg(pxh[h] + k) : 0.f;         \
        }                                                                       \
    }
#define STSA(st)                                                                \
    {                                                                           \
        _Pragma("unroll")                                                       \
        for (int h = 0; h < 2; h++)                                             \
            *(uint2*)&As[st][rA + 32 * h][4 * g] =                              \
                make_uint2(packbf(aF[h][0], aF[h][1]), packbf(aF[h][2], aF[h][3])); \
    }
#define LDB_CPA(st, k0)                                                         \
    {                                                                           \
        _Pragma("unroll")                                                       \
        for (int q = 0; q < 4; q++) {                                           \
            int c = tid + 256 * q;                                              \
            int brow = c >> 5, bcol = (c & 31) * 8;                             \
            int gk = (k0) + brow;                                               \
            bool p = (gk < KDIM);                                               \
            unsigned db = (unsigned)__cvta_generic_to_shared(&Bs[st][brow][bcol]); \
            cpa16(db, d_Wb + (size_t)(p ? gk : 0) * HC + bcol, p);              \
        }                                                                       \
        asm volatile("cp.async.commit_group;\n");                               \
    }

    LDGA(0)
    LDB_CPA(0, 0)
    STSA(0)
    asm volatile("cp.async.wait_group 0;\n");
    __syncthreads();

    for (int it = 0; it < NIT; it++) {
        const int s = it & 1;
        if (it + 1 < NIT) {
            LDGA((it + 1) * BK)
            LDB_CPA(s ^ 1, (it + 1) * BK)      // async into the idle buffer
        }

#pragma unroll
        for (int kk = 0; kk < BK; kk += 16) {
            unsigned a[2][4], bq[4][4];
#pragma unroll
            for (int i = 0; i < 2; i++) {
                unsigned ad = (unsigned)__cvta_generic_to_shared(
                    &As[s][wm + i * 16 + (lane & 15)][kk + (lane >> 4) * 8]);
                ldsm_x4(a[i][0], a[i][1], a[i][2], a[i][3], ad);
            }
#pragma unroll
            for (int j = 0; j < 4; j++) {
                unsigned ad = (unsigned)__cvta_generic_to_shared(
                    &Bs[s][kk + (lane & 15)][wn + j * 16 + (lane >> 4) * 8]);
                ldsm_x4t(bq[j][0], bq[j][1], bq[j][2], bq[j][3], ad);
            }
#pragma unroll
            for (int i = 0; i < 2; i++)
#pragma unroll
                for (int j = 0; j < 4; j++) {
                    mma_bf16(acc[i][2 * j], a[i][0], a[i][1], a[i][2], a[i][3],
                             bq[j][0], bq[j][1]);
                    mma_bf16(acc[i][2 * j + 1], a[i][0], a[i][1], a[i][2], a[i][3],
                             bq[j][2], bq[j][3]);
                }
        }

        if (it + 1 < NIT) {
            STSA(s ^ 1)                        // s^1 readers done before last sync
            asm volatile("cp.async.wait_group 0;\n");
            __syncthreads();
        }
    }
#undef LDGA
#undef STSA
#undef LDB_CPA

    // Epilogue: bf16x2 stores + fused attention dots (fp32 accumulators).
    float psA[2] = {0.f, 0.f}, pdA[2] = {0.f, 0.f};
    float psB[2] = {0.f, 0.f}, pdB[2] = {0.f, 0.f};
#pragma unroll
    for (int i = 0; i < 2; i++) {
        int r0 = row0 + wm + i * 16 + gid;
#pragma unroll
        for (int j = 0; j < 8; j++) {
            int c = wn + j * 8 + tig * 2;
            float avs0 = sAtt[0][c], avs1 = sAtt[0][c + 1];
            float avd0 = sAtt[1][c], avd1 = sAtt[1][c + 1];
            psA[i] += acc[i][j].x * avs0 + acc[i][j].y * avs1;
            pdA[i] += acc[i][j].x * avd0 + acc[i][j].y * avd1;
            psB[i] += acc[i][j].z * avs0 + acc[i][j].w * avs1;
            pdB[i] += acc[i][j].z * avd0 + acc[i][j].w * avd1;
            if (r0 < NN)
                d_xpb[((size_t)r0 * HC + c) >> 1] =
                    __float22bfloat162_rn(make_float2(acc[i][j].x, acc[i][j].y));
            if (r0 + 8 < NN)
                d_xpb[((size_t)(r0 + 8) * HC + c) >> 1] =
                    __float22bfloat162_rn(make_float2(acc[i][j].z, acc[i][j].w));
        }
    }
#pragma unroll
    for (int i = 0; i < 2; i++) {
        psA[i] += __shfl_xor_sync(0xffffffffu, psA[i], 1);
        psA[i] += __shfl_xor_sync(0xffffffffu, psA[i], 2);
        pdA[i] += __shfl_xor_sync(0xffffffffu, pdA[i], 1);
        pdA[i] += __shfl_xor_sync(0xffffffffu, pdA[i], 2);
        psB[i] += __shfl_xor_sync(0xffffffffu, psB[i], 1);
        psB[i] += __shfl_xor_sync(0xffffffffu, psB[i], 2);
        pdB[i] += __shfl_xor_sync(0xffffffffu, pdB[i], 1);
        pdB[i] += __shfl_xor_sync(0xffffffffu, pdB[i], 2);
        if (tig == 0) {
            int r0 = row0 + wm + i * 16 + gid;
            if (r0 < NN) {
                ((float*)&d_asrc[r0])[hd] = psA[i];
                ((float*)&d_adst[r0])[hd] = pdA[i];
            }
            if (r0 + 8 < NN) {
                ((float*)&d_asrc[r0 + 8])[hd] = psB[i];
                ((float*)&d_adst[r0 + 8])[hd] = pdB[i];
            }
        }
    }
}

// Exclusive scan of (deg+1) -> rowptr phase 1; resets d_deg for next run.
__global__ void __launch_bounds__(1024) k_scan1() {
    __shared__ int sh[1024];
    int i = blockIdx.x * 1024 + threadIdx.x;
    int v = 0;
    if (i < NN) {
        v = d_deg[i] + 1;          // +1 = self loop
        d_deg[i] = 0;              // consumer-reset
    }
    sh[threadIdx.x] = v;
    __syncthreads();
    for (int off = 1; off < 1024; off <<= 1) {
        int t = 0;
        if (threadIdx.x >= off) t = sh[threadIdx.x - off];
        __syncthreads();
        sh[threadIdx.x] += t;
        __syncthreads();
    }
    if (i < NN) d_rowptr[i] = sh[threadIdx.x] - v;
    if (threadIdx.x == 1023) d_bsum[blockIdx.x] = sh[1023];
}

// Phase 2+3 merged: every block redundantly prefix-sums the 98 block sums
// in smem (thread 0, ~100 adds), then applies its offset.
__global__ void k_scan3(int nblk) {
    __shared__ int sb[128];
    if (threadIdx.x < nblk) sb[threadIdx.x] = d_bsum[threadIdx.x];
    __syncthreads();
    if (threadIdx.x == 0) {
        int run = 0;
        for (int b = 0; b < nblk; b++) { int t = sb[b]; sb[b] = run; run += t; }
    }
    __syncthreads();
    int i = blockIdx.x * blockDim.x + threadIdx.x;
    if (i < NN) d_rowptr[i] += sb[i >> 10];
    if (i == 0) d_rowptr[NN] = ENQ;
}

// Edge pass, 2 edges/thread (ENQ even, EE even -> pairs never straddle the
// real/self-loop boundary). ex = exp(leaky(logit)); scatter packed
// {src, ex(bf16x4)} with one atomic (on d_rowptr[d] itself) + one 16B store
// per edge. (segment-max skipped: logits O(1), exp cannot overflow.)
__global__ void k_edge(const void* __restrict__ ei) {
    int e = (blockIdx.x * blockDim.x + threadIdx.x) * 2;
    if (e >= ENQ) return;
    int s0, d0, s1, d1;
    if (e < EE) {
        if (d_flag32) {
            const int* p = (const int*)ei;
            int2 sv = *(const int2*)(p + e);
            int2 dv = *(const int2*)(p + EE + e);
            s0 = sv.x; s1 = sv.y; d0 = dv.x; d1 = dv.y;
        } else {
            const long long* p = (const long long*)ei;
            longlong2 sv = *(const longlong2*)(p + e);
            longlong2 dv = *(const longlong2*)(p + EE + e);
            s0 = (int)sv.x; s1 = (int)sv.y; d0 = (int)dv.x; d1 = (int)dv.y;
        }
    } else {
        s0 = d0 = e - EE;
        s1 = d1 = e + 1 - EE;
    }
    float4 as0 = d_asrc[s0], ad0 = d_adst[d0];
    float4 as1 = d_asrc[s1], ad1 = d_adst[d1];
    uint4 sl0, sl1;
    sl0.x = (unsigned)s0;
    sl0.y = packbf(__expf(lrelu(as0.x + ad0.x)), __expf(lrelu(as0.y + ad0.y)));
    sl0.z = packbf(__expf(lrelu(as0.z + ad0.z)), __expf(lrelu(as0.w + ad0.w)));
    sl0.w = 0u;
    sl1.x = (unsigned)s1;
    sl1.y = packbf(__expf(lrelu(as1.x + ad1.x)), __expf(lrelu(as1.y + ad1.y)));
    sl1.z = packbf(__expf(lrelu(as1.z + ad1.z)), __expf(lrelu(as1.w + ad1.w)));
    sl1.w = 0u;
    int slot0 = atomicAdd(&d_rowptr[d0], 1);
    d_slot[slot0] = sl0;
    int slot1 = atomicAdd(&d_rowptr[d1], 1);
    d_slot[slot1] = sl1;
}

// Per-node aggregation: ONE WARP per node; lane owns bf16x2 column pair per
// head. Warp-uniform slot pair loads software-pipelined one iteration ahead;
// xp gathers coalesced 64B per head. Local denominator; divide once.
__global__ void __launch_bounds__(256) k_agg(const void* __restrict__ batch,
                                             const float* __restrict__ bias) {
    int n = blockIdx.x * 8 + (threadIdx.x >> 5);
    int lane = threadIdx.x & 31;
    if (n >= NN) return;
    int beg = (n == 0) ? 0 : d_rowptr[n - 1];
    int end = d_rowptr[n];
    float2 a0 = {0.f, 0.f}, a1 = {0.f, 0.f}, a2 = {0.f, 0.f}, a3 = {0.f, 0.f};
    float dn0 = 0.f, dn1 = 0.f, dn2 = 0.f, dn3 = 0.f;
    int i = beg;
    if (i + 2 <= end) {
        uint4 slA = d_slot[i];
        uint4 slB = d_slot[i + 1];
        while (true) {
            int nx = i + 2;
            bool more = (nx + 2 <= end);
            uint4 nA, nB;
            if (more) { nA = d_slot[nx]; nB = d_slot[nx + 1]; }
            const __nv_bfloat162* xrA = &d_xpb[(size_t)(int)slA.x * HC / 2];
            const __nv_bfloat162* xrB = &d_xpb[(size_t)(int)slB.x * HC / 2];
            float2 uA0 = bf2f(xrA[lane]),      uB0 = bf2f(xrB[lane]);
            float2 uA1 = bf2f(xrA[32 + lane]), uB1 = bf2f(xrB[32 + lane]);
            float2 uA2 = bf2f(xrA[64 + lane]), uB2 = bf2f(xrB[64 + lane]);
            float2 uA3 = bf2f(xrA[96 + lane]), uB3 = bf2f(xrB[96 + lane]);
            float2 eA01 = bf2f(*(__nv_bfloat162*)&slA.y);
            float2 eA23 = bf2f(*(__nv_bfloat162*)&slA.z);
            float2 eB01 = bf2f(*(__nv_bfloat162*)&slB.y);
            float2 eB23 = bf2f(*(__nv_bfloat162*)&slB.z);
            dn0 += eA01.x + eB01.x; dn1 += eA01.y + eB01.y;
            dn2 += eA23.x + eB23.x; dn3 += eA23.y + eB23.y;
            a0.x += eA01.x * uA0.x + eB01.x * uB0.x; a0.y += eA01.x * uA0.y + eB01.x * uB0.y;
            a1.x += eA01.y * uA1.x + eB01.y * uB1.x; a1.y += eA01.y * uA1.y + eB01.y * uB1.y;
            a2.x += eA23.x * uA2.x + eB23.x * uB2.x; a2.y += eA23.x * uA2.y + eB23.x * uB2.y;
            a3.x += eA23.y * uA3.x + eB23.y * uB3.x; a3.y += eA23.y * uA3.y + eB23.y * uB3.y;
            i = nx;
            if (!more) break;
            slA = nA; slB = nB;
        }
    }
    if (i < end) {
        uint4 sl = d_slot[i];
        const __nv_bfloat162* xr = &d_xpb[(size_t)(int)sl.x * HC / 2];
        float2 al01 = bf2f(*(__nv_bfloat162*)&sl.y);
        float2 al23 = bf2f(*(__nv_bfloat162*)&sl.z);
        dn0 += al01.x; dn1 += al01.y; dn2 += al23.x; dn3 += al23.y;
        float2 v0 = bf2f(xr[lane]);
        float2 v1 = bf2f(xr[32 + lane]);
        float2 v2 = bf2f(xr[64 + lane]);
        float2 v3 = bf2f(xr[96 + lane]);
        a0.x += al01.x * v0.x; a0.y += al01.x * v0.y;
        a1.x += al01.y * v1.x; a1.y += al01.y * v1.y;
        a2.x += al23.x * v2.x; a2.y += al23.x * v2.y;
        a3.x += al23.y * v3.x; a3.y += al23.y * v3.y;
    }
    float2 bv = ((const float2*)bias)[lane];
    float hv0 = 0.25f * (a0.x / dn0 + a1.x / dn1 + a2.x / dn2 + a3.x / dn3) + bv.x;
    float hv1 = 0.25f * (a0.y / dn0 + a1.y / dn1 + a2.y / dn2 + a3.y / dn3) + bv.y;
    hv0 = fmaxf(hv0, 0.f);
    hv1 = fmaxf(hv1, 0.f);
    int g = batch_of(batch, n);
    atomicAdd(&d_gsum[g * 64 + 2 * lane], hv0);
    atomicAdd(&d_gsum[g * 64 + 2 * lane + 1], hv1);
    if (lane == 0) atomicAdd(&d_gcnt[g], 1);
}

// Head MLP: one block per graph. Also consumer-resets gsum/gcnt/flag32.
__global__ void k_mlp(const float* __restrict__ w1, const float* __restrict__ b1,
                      const float* __restrict__ w2, const float* __restrict__ b2,
                      float* __restrict__ out) {
    __shared__ float sg[64], sz[64];
    int g = blockIdx.x, c = threadIdx.x;
    float cnt = (float)d_gcnt[g];
    if (cnt < 1.f) cnt = 1.f;
    sg[c] = d_gsum[g * 64 + c] / cnt;
    __syncthreads();
    d_gsum[g * 64 + c] = 0.f;                 // consumer-reset
    if (c == 0) d_gcnt[g] = 0;
    if (g == 0 && c == 0) d_flag32 = 0;
    float z = b1[c];
#pragma unroll 16
    for (int k = 0; k < 64; k++) z += sg[k] * w1[k * 64 + c];
    z = fmaxf(z, 0.f);
    sz[c] = z * w2[c];
    __syncthreads();
    if (c < 32) {
        float v = sz[c] + sz[c + 32];
#pragma unroll
        for (int o = 16; o; o >>= 1) v += __shfl_down_sync(0xffffffffu, v, o);
        if (c == 0) out[g] = 1.f / (1.f + expf(-(v + b2[0])));
    }
}

// ---------------- launcher ----------------
extern "C" void kernel_launch(void* const* d_in, const int* in_sizes, int n_in,
                              void* d_out, int out_size) {
    const float* x     = (const float*)d_in[0];
    const float* W     = (const float*)d_in[1];
    const float* att_s = (const float*)d_in[2];
    const float* att_d = (const float*)d_in[3];
    const float* bias  = (const float*)d_in[4];
    const float* w1    = (const float*)d_in[5];
    const float* b1    = (const float*)d_in[6];
    const float* w2    = (const float*)d_in[7];
    const float* b2    = (const float*)d_in[8];
    const void*  ei    = d_in[9];
    const void*  batch = d_in[10];
    float* out = (float*)d_out;

    k_wprep<<<(KDIM * HC / 4 + 255) / 256, 256>>>(W);
    k_gemm_tc<<<(NN + BM - 1) / BM, 256>>>(x, att_s, att_d);
    k_detect<<<128, 256>>>((const unsigned*)ei);
    k_deg<<<(EE / 2 + 255) / 256, 256>>>(ei);                  // profile slot 4
    int scan_blks = (NN + 1023) / 1024;
    k_scan1<<<scan_blks, 1024>>>();
    k_scan3<<<(NN + 255) / 256, 256>>>(scan_blks);
    k_edge<<<(ENQ / 2 + 255) / 256, 256>>>(ei);
    k_agg<<<(NN + 7) / 8, 256>>>(batch, bias);
    k_mlp<<<GGR, 64>>>(w1, b1, w2, b2, out);
}

// round 13
// speedup vs baseline: 1.0904x; 1.0274x over previous
#include <cuda_runtime.h>
#include <cuda_bf16.h>

// Problem constants (fixed by the reference)
#define NN 100000
#define EE 1600000
#define ENQ 1700000        // EE + NN (edges + self loops)
#define GGR 128
#define KDIM 329
#define HC 256             // H*C = 4*64

// GEMM tiling: single pass over all 256 columns
#define BM 64
#define BN 256
#define BK 32
#define NIT ((KDIM + BK - 1) / BK)   // 11

// ---------------- static device scratch (no cudaMalloc allowed) ----------------
__device__ __nv_bfloat162 d_xpb[(size_t)NN * HC / 2]; // [N, H*C] projected feats, bf16
__device__ __nv_bfloat16  d_Wb[KDIM * HC];            // W in bf16 (k_wprep)
__device__ float4 d_asrc[NN];             // a_src[n][4]
__device__ float4 d_adst[NN];             // a_dst[n][4]
__device__ uint4  d_slot[ENQ];            // CSR slot: {src, ex01(bf16x2), ex23(bf16x2), 0}
__device__ int    d_deg[NN];              // zero at rest; reset by k_scan1
__device__ int    d_rowptr[NN + 1];       // rebuilt every run by scans
__device__ int    d_bsum[128];
__device__ float  d_gsum[GGR * 64];       // zero at rest; reset by k_mlp
__device__ int    d_gcnt[GGR];            // zero at rest; reset by k_mlp
__device__ int    d_flag32;               // 1 if int32 inputs; reset by k_mlp

// ---------------- helpers ----------------
__device__ __forceinline__ int2 edge_sd(const void* ei, int e) {
    if (d_flag32) {
        const int* p = (const int*)ei;
        return make_int2(p[e], p[EE + e]);
    } else {
        const long long* p = (const long long*)ei;
        return make_int2((int)p[e], (int)p[EE + e]);
    }
}
__device__ __forceinline__ int batch_of(const void* b, int n) {
    if (d_flag32) return ((const int*)b)[n];
    return (int)((const long long*)b)[n];
}
__device__ __forceinline__ float lrelu(float v) { return v > 0.f ? v : 0.2f * v; }
__device__ __forceinline__ float2 bf2f(__nv_bfloat162 v) { return __bfloat1622float2(v); }
__device__ __forceinline__ unsigned packbf(float a, float b) {
    __nv_bfloat162 p = __float22bfloat162_rn(make_float2(a, b));
    return *(unsigned*)&p;
}
__device__ __forceinline__ void cpa16(unsigned dst, const void* src, bool p) {
    int sz = p ? 16 : 0;
    asm volatile("cp.async.cg.shared.global [%0], [%1], 16, %2;\n"
                 :: "r"(dst), "l"(src), "r"(sz));
}
__device__ __forceinline__ void ldsm_x4(unsigned& r0, unsigned& r1, unsigned& r2, unsigned& r3,
                                        unsigned addr) {
    asm volatile("ldmatrix.sync.aligned.m8n8.x4.shared.b16 {%0,%1,%2,%3}, [%4];"
                 : "=r"(r0), "=r"(r1), "=r"(r2), "=r"(r3) : "r"(addr));
}
__device__ __forceinline__ void ldsm_x4t(unsigned& r0, unsigned& r1, unsigned& r2, unsigned& r3,
                                         unsigned addr) {
    asm volatile("ldmatrix.sync.aligned.m8n8.x4.trans.shared.b16 {%0,%1,%2,%3}, [%4];"
                 : "=r"(r0), "=r"(r1), "=r"(r2), "=r"(r3) : "r"(addr));
}
__device__ __forceinline__ void mma_bf16(float4& d,
                                         unsigned a0, unsigned a1, unsigned a2, unsigned a3,
                                         unsigned b0, unsigned b1) {
    asm volatile(
        "mma.sync.aligned.m16n8k16.row.col.f32.bf16.bf16.f32 "
        "{%0,%1,%2,%3}, {%4,%5,%6,%7}, {%8,%9}, {%0,%1,%2,%3};\n"
        : "+f"(d.x), "+f"(d.y), "+f"(d.z), "+f"(d.w)
        : "r"(a0), "r"(a1), "r"(a2), "r"(a3), "r"(b0), "r"(b1));
}

// ---------------- kernels ----------------
// Detect int32 vs int64: in an int64 LE array the odd 32-bit words (hi) are all 0.
// uint4 loads cover 2 int64 (hi words at .y and .w). EE*2 ints = 400K uint4s.
__global__ void k_detect(const uint4* __restrict__ ei) {
    int i = blockIdx.x * blockDim.x + threadIdx.x;
    bool nz = false;
    for (int q = i; q < EE / 2; q += gridDim.x * blockDim.x) {
        uint4 v = ei[q];
        nz |= (v.y | v.w) != 0u;
    }
    unsigned b = __ballot_sync(0xffffffffu, nz);
    if ((threadIdx.x & 31) == 0 && b) atomicOr(&d_flag32, 1);
}

// W fp32 -> bf16.
__global__ void k_wprep(const float* __restrict__ W) {
    int i = blockIdx.x * 256 + threadIdx.x;          // float4 groups
    if (i * 4 < KDIM * HC) {
        float4 v = ((const float4*)W)[i];
        *(uint2*)&d_Wb[i * 4] = make_uint2(packbf(v.x, v.y), packbf(v.z, v.w));
    }
}

// Degree histogram, 2 edges/thread (EE even -> pairs aligned & in-bounds).
__global__ void k_deg(const void* __restrict__ ei) {
    int e = (blockIdx.x * blockDim.x + threadIdx.x) * 2;
    if (e >= EE) return;
    int d0, d1;
    if (d_flag32) {
        int2 dv = *(const int2*)((const int*)ei + EE + e);
        d0 = dv.x; d1 = dv.y;
    } else {
        longlong2 dv = *(const longlong2*)((const long long*)ei + EE + e);
        d0 = (int)dv.x; d1 = (int)dv.y;
    }
    atomicAdd(&d_deg[d0], 1);
    atomicAdd(&d_deg[d1], 1);
}

// Tensor-core GEMM: xp = x @ W via bf16 mma.m16n8k16 + ldmatrix.
// A: scalar LDG (x rows only 4B-aligned) -> pack -> STS.64.
// B: cp.async 16B direct from pre-converted d_Wb.
// Attention dots fused in the epilogue. Block 64x256, 8 warps (2M x 4N).
__global__ void __launch_bounds__(256) k_gemm_tc(const float* __restrict__ x,
                                                 const float* __restrict__ att_s,
                                                 const float* __restrict__ att_d) {
    __shared__ __align__(16) __nv_bfloat16 As[2][BM][BK + 8];   // row 80B
    __shared__ __align__(16) __nv_bfloat16 Bs[2][BK][BN + 8];   // row 528B
    __shared__ float sAtt[2][HC];
    const int tid = threadIdx.x;
    const int lane = tid & 31, wid = tid >> 5;
    const int wm = (wid & 1) * 32;
    const int wn = (wid >> 1) * 64;
    const int hd = wid >> 1;                       // head of this warp's col slice
    const int gid = lane >> 2, tig = lane & 3;
    const int row0 = blockIdx.x * BM;

    sAtt[0][tid] = att_s[tid];
    sAtt[1][tid] = att_d[tid];

    // A staging: lane g = tid&7 owns k in [4g, 4g+4); row rA = tid>>3 (+32 for h=1).
    const int g = tid & 7, rA = tid >> 3;
    bool rokh[2]; const float* pxh[2];
#pragma unroll
    for (int h = 0; h < 2; h++) {
        int gr = row0 + rA + 32 * h;
        rokh[h] = (gr < NN);
        pxh[h] = x + (size_t)(rokh[h] ? gr : 0) * KDIM;
    }

    float aF[2][4];
    float4 acc[2][8];
#pragma unroll
    for (int i = 0; i < 2; i++)
#pragma unroll
        for (int j = 0; j < 8; j++) acc[i][j] = make_float4(0.f, 0.f, 0.f, 0.f);

#define LDGA(k0)                                                                \
    {                                                                           \
        _Pragma("unroll")                                                       \
        for (int h = 0; h < 2; h++)                                             \
        _Pragma("unroll")                                                       \
        for (int q = 0; q < 4; q++) {                                           \
            int k = (k0) + 4 * g + q;                                           \
            aF[h][q] = (rokh[h] && k < KDIM) ? __ldg(pxh[h] + k) : 0.f;         \
        }                                                                       \
    }
#define STSA(st)                                                                \
    {                                                                           \
        _Pragma("unroll")                                                       \
        for (int h = 0; h < 2; h++)                                             \
            *(uint2*)&As[st][rA + 32 * h][4 * g] =                              \
                make_uint2(packbf(aF[h][0], aF[h][1]), packbf(aF[h][2], aF[h][3])); \
    }
#define LDB_CPA(st, k0)                                                         \
    {                                                                           \
        _Pragma("unroll")                                                       \
        for (int q = 0; q < 4; q++) {                                           \
            int c = tid + 256 * q;                                              \
            int brow = c >> 5, bcol = (c & 31) * 8;                             \
            int gk = (k0) + brow;                                               \
            bool p = (gk < KDIM);                                               \
            unsigned db = (unsigned)__cvta_generic_to_shared(&Bs[st][brow][bcol]); \
            cpa16(db, d_Wb + (size_t)(p ? gk : 0) * HC + bcol, p);              \
        }                                                                       \
        asm volatile("cp.async.commit_group;\n");                               \
    }

    LDGA(0)
    LDB_CPA(0, 0)
    STSA(0)
    asm volatile("cp.async.wait_group 0;\n");
    __syncthreads();

    for (int it = 0; it < NIT; it++) {
        const int s = it & 1;
        if (it + 1 < NIT) {
            LDGA((it + 1) * BK)
            LDB_CPA(s ^ 1, (it + 1) * BK)      // async into the idle buffer
        }

#pragma unroll
        for (int kk = 0; kk < BK; kk += 16) {
            unsigned a[2][4], bq[4][4];
#pragma unroll
            for (int i = 0; i < 2; i++) {
                unsigned ad = (unsigned)__cvta_generic_to_shared(
                    &As[s][wm + i * 16 + (lane & 15)][kk + (lane >> 4) * 8]);
                ldsm_x4(a[i][0], a[i][1], a[i][2], a[i][3], ad);
            }
#pragma unroll
            for (int j = 0; j < 4; j++) {
                unsigned ad = (unsigned)__cvta_generic_to_shared(
                    &Bs[s][kk + (lane & 15)][wn + j * 16 + (lane >> 4) * 8]);
                ldsm_x4t(bq[j][0], bq[j][1], bq[j][2], bq[j][3], ad);
            }
#pragma unroll
            for (int i = 0; i < 2; i++)
#pragma unroll
                for (int j = 0; j < 4; j++) {
                    mma_bf16(acc[i][2 * j], a[i][0], a[i][1], a[i][2], a[i][3],
                             bq[j][0], bq[j][1]);
                    mma_bf16(acc[i][2 * j + 1], a[i][0], a[i][1], a[i][2], a[i][3],
                             bq[j][2], bq[j][3]);
                }
        }

        if (it + 1 < NIT) {
            STSA(s ^ 1)                        // s^1 readers done before last sync
            asm volatile("cp.async.wait_group 0;\n");
            __syncthreads();
        }
    }
#undef LDGA
#undef STSA
#undef LDB_CPA

    // Epilogue: bf16x2 stores + fused attention dots (fp32 accumulators).
    float psA[2] = {0.f, 0.f}, pdA[2] = {0.f, 0.f};
    float psB[2] = {0.f, 0.f}, pdB[2] = {0.f, 0.f};
#pragma unroll
    for (int i = 0; i < 2; i++) {
        int r0 = row0 + wm + i * 16 + gid;
#pragma unroll
        for (int j = 0; j < 8; j++) {
            int c = wn + j * 8 + tig * 2;
            float avs0 = sAtt[0][c], avs1 = sAtt[0][c + 1];
            float avd0 = sAtt[1][c], avd1 = sAtt[1][c + 1];
            psA[i] += acc[i][j].x * avs0 + acc[i][j].y * avs1;
            pdA[i] += acc[i][j].x * avd0 + acc[i][j].y * avd1;
            psB[i] += acc[i][j].z * avs0 + acc[i][j].w * avs1;
            pdB[i] += acc[i][j].z * avd0 + acc[i][j].w * avd1;
            if (r0 < NN)
                d_xpb[((size_t)r0 * HC + c) >> 1] =
                    __float22bfloat162_rn(make_float2(acc[i][j].x, acc[i][j].y));
            if (r0 + 8 < NN)
                d_xpb[((size_t)(r0 + 8) * HC + c) >> 1] =
                    __float22bfloat162_rn(make_float2(acc[i][j].z, acc[i][j].w));
        }
    }
#pragma unroll
    for (int i = 0; i < 2; i++) {
        psA[i] += __shfl_xor_sync(0xffffffffu, psA[i], 1);
        psA[i] += __shfl_xor_sync(0xffffffffu, psA[i], 2);
        pdA[i] += __shfl_xor_sync(0xffffffffu, pdA[i], 1);
        pdA[i] += __shfl_xor_sync(0xffffffffu, pdA[i], 2);
        psB[i] += __shfl_xor_sync(0xffffffffu, psB[i], 1);
        psB[i] += __shfl_xor_sync(0xffffffffu, psB[i], 2);
        pdB[i] += __shfl_xor_sync(0xffffffffu, pdB[i], 1);
        pdB[i] += __shfl_xor_sync(0xffffffffu, pdB[i], 2);
        if (tig == 0) {
            int r0 = row0 + wm + i * 16 + gid;
            if (r0 < NN) {
                ((float*)&d_asrc[r0])[hd] = psA[i];
                ((float*)&d_adst[r0])[hd] = pdA[i];
            }
            if (r0 + 8 < NN) {
                ((float*)&d_asrc[r0 + 8])[hd] = psB[i];
                ((float*)&d_adst[r0 + 8])[hd] = pdB[i];
            }
        }
    }
}

// Exclusive scan of (deg+1) -> rowptr phase 1; resets d_deg for next run.
__global__ void __launch_bounds__(1024) k_scan1() {
    __shared__ int sh[1024];
    int i = blockIdx.x * 1024 + threadIdx.x;
    int v = 0;
    if (i < NN) {
        v = d_deg[i] + 1;          // +1 = self loop
        d_deg[i] = 0;              // consumer-reset
    }
    sh[threadIdx.x] = v;
    __syncthreads();
    for (int off = 1; off < 1024; off <<= 1) {
        int t = 0;
        if (threadIdx.x >= off) t = sh[threadIdx.x - off];
        __syncthreads();
        sh[threadIdx.x] += t;
        __syncthreads();
    }
    if (i < NN) d_rowptr[i] = sh[threadIdx.x] - v;
    if (threadIdx.x == 1023) d_bsum[blockIdx.x] = sh[1023];
}

// Phase 2+3 merged: every block redundantly prefix-sums the block sums in smem,
// then applies its offset.
__global__ void k_scan3(int nblk) {
    __shared__ int sb[128];
    if (threadIdx.x < nblk) sb[threadIdx.x] = d_bsum[threadIdx.x];
    __syncthreads();
    if (threadIdx.x == 0) {
        int run = 0;
        for (int b = 0; b < nblk; b++) { int t = sb[b]; sb[b] = run; run += t; }
    }
    __syncthreads();
    int i = blockIdx.x * blockDim.x + threadIdx.x;
    if (i < NN) d_rowptr[i] += sb[i >> 10];
    if (i == 0) d_rowptr[NN] = ENQ;
}

// Single edge pass (1 edge/thread — measured best): ex = exp(leaky(logit));
// scatter packed {src, ex(bf16x4)} with ONE 16B store and ONE atomic (on
// d_rowptr[d] itself; post-pass rowptr[n] == original rowptr[n+1]).
// (segment-max skipped: logits O(1), exp cannot overflow; softmax identical.)
__global__ void k_edge(const void* __restrict__ ei) {
    int e = blockIdx.x * blockDim.x + threadIdx.x;
    if (e >= ENQ) return;
    int s, d;
    if (e < EE) { int2 sd = edge_sd(ei, e); s = sd.x; d = sd.y; }
    else { s = d = e - EE; }
    float4 as = d_asrc[s], ad = d_adst[d];
    float ex0 = __expf(lrelu(as.x + ad.x));
    float ex1 = __expf(lrelu(as.y + ad.y));
    float ex2 = __expf(lrelu(as.z + ad.z));
    float ex3 = __expf(lrelu(as.w + ad.w));
    int slot = atomicAdd(&d_rowptr[d], 1);
    uint4 sl;
    sl.x = (unsigned)s;
    sl.y = packbf(ex0, ex1);
    sl.z = packbf(ex2, ex3);
    sl.w = 0u;
    d_slot[slot] = sl;
}

// Per-node aggregation (measured best): ONE WARP per node; lane owns bf16x2
// column pair per head. Slot loads warp-uniform; xp gathers coalesced.
// 2-way unroll; local denominator; divide once at the end.
__global__ void __launch_bounds__(256) k_agg(const void* __restrict__ batch,
                                             const float* __restrict__ bias) {
    int n = blockIdx.x * 8 + (threadIdx.x >> 5);
    int lane = threadIdx.x & 31;
    if (n >= NN) return;
    int beg = (n == 0) ? 0 : d_rowptr[n - 1];
    int end = d_rowptr[n];
    float2 a0 = {0.f, 0.f}, a1 = {0.f, 0.f}, a2 = {0.f, 0.f}, a3 = {0.f, 0.f};
    float dn0 = 0.f, dn1 = 0.f, dn2 = 0.f, dn3 = 0.f;
    int i = beg;
    for (; i + 2 <= end; i += 2) {
        uint4 slA = d_slot[i];
        uint4 slB = d_slot[i + 1];
        const __nv_bfloat162* xrA = &d_xpb[(size_t)(int)slA.x * HC / 2];
        const __nv_bfloat162* xrB = &d_xpb[(size_t)(int)slB.x * HC / 2];
        float2 uA0 = bf2f(xrA[lane]),      uB0 = bf2f(xrB[lane]);
        float2 uA1 = bf2f(xrA[32 + lane]), uB1 = bf2f(xrB[32 + lane]);
        float2 uA2 = bf2f(xrA[64 + lane]), uB2 = bf2f(xrB[64 + lane]);
        float2 uA3 = bf2f(xrA[96 + lane]), uB3 = bf2f(xrB[96 + lane]);
        float2 eA01 = bf2f(*(__nv_bfloat162*)&slA.y);
        float2 eA23 = bf2f(*(__nv_bfloat162*)&slA.z);
        float2 eB01 = bf2f(*(__nv_bfloat162*)&slB.y);
        float2 eB23 = bf2f(*(__nv_bfloat162*)&slB.z);
        dn0 += eA01.x + eB01.x; dn1 += eA01.y + eB01.y;
        dn2 += eA23.x + eB23.x; dn3 += eA23.y + eB23.y;
        a0.x += eA01.x * uA0.x + eB01.x * uB0.x; a0.y += eA01.x * uA0.y + eB01.x * uB0.y;
        a1.x += eA01.y * uA1.x + eB01.y * uB1.x; a1.y += eA01.y * uA1.y + eB01.y * uB1.y;
        a2.x += eA23.x * uA2.x + eB23.x * uB2.x; a2.y += eA23.x * uA2.y + eB23.x * uB2.y;
        a3.x += eA23.y * uA3.x + eB23.y * uB3.x; a3.y += eA23.y * uA3.y + eB23.y * uB3.y;
    }
    if (i < end) {
        uint4 sl = d_slot[i];
        const __nv_bfloat162* xr = &d_xpb[(size_t)(int)sl.x * HC / 2];
        float2 al01 = bf2f(*(__nv_bfloat162*)&sl.y);
        float2 al23 = bf2f(*(__nv_bfloat162*)&sl.z);
        dn0 += al01.x; dn1 += al01.y; dn2 += al23.x; dn3 += al23.y;
        float2 v0 = bf2f(xr[lane]);
        float2 v1 = bf2f(xr[32 + lane]);
        float2 v2 = bf2f(xr[64 + lane]);
        float2 v3 = bf2f(xr[96 + lane]);
        a0.x += al01.x * v0.x; a0.y += al01.x * v0.y;
        a1.x += al01.y * v1.x; a1.y += al01.y * v1.y;
        a2.x += al23.x * v2.x; a2.y += al23.x * v2.y;
        a3.x += al23.y * v3.x; a3.y += al23.y * v3.y;
    }
    float2 bv = ((const float2*)bias)[lane];
    float hv0 = 0.25f * (a0.x / dn0 + a1.x / dn1 + a2.x / dn2 + a3.x / dn3) + bv.x;
    float hv1 = 0.25f * (a0.y / dn0 + a1.y / dn1 + a2.y / dn2 + a3.y / dn3) + bv.y;
    hv0 = fmaxf(hv0, 0.f);
    hv1 = fmaxf(hv1, 0.f);
    int g = batch_of(batch, n);
    atomicAdd(&d_gsum[g * 64 + 2 * lane], hv0);
    atomicAdd(&d_gsum[g * 64 + 2 * lane + 1], hv1);
    if (lane == 0) atomicAdd(&d_gcnt[g], 1);
}

// Head MLP: one block per graph. Also consumer-resets gsum/gcnt/flag32.
__global__ void k_mlp(const float* __restrict__ w1, const float* __restrict__ b1,
                      const float* __restrict__ w2, const float* __restrict__ b2,
                      float* __restrict__ out) {
    __shared__ float sg[64], sz[64];
    int g = blockIdx.x, c = threadIdx.x;
    float cnt = (float)d_gcnt[g];
    if (cnt < 1.f) cnt = 1.f;
    sg[c] = d_gsum[g * 64 + c] / cnt;
    __syncthreads();
    d_gsum[g * 64 + c] = 0.f;                 // consumer-reset
    if (c == 0) d_gcnt[g] = 0;
    if (g == 0 && c == 0) d_flag32 = 0;
    float z = b1[c];
#pragma unroll 16
    for (int k = 0; k < 64; k++) z += sg[k] * w1[k * 64 + c];
    z = fmaxf(z, 0.f);
    sz[c] = z * w2[c];
    __syncthreads();
    if (c < 32) {
        float v = sz[c] + sz[c + 32];
#pragma unroll
        for (int o = 16; o; o >>= 1) v += __shfl_down_sync(0xffffffffu, v, o);
        if (c == 0) out[g] = 1.f / (1.f + expf(-(v + b2[0])));
    }
}

// ---------------- launcher ----------------
extern "C" void kernel_launch(void* const* d_in, const int* in_sizes, int n_in,
                              void* d_out, int out_size) {
    const float* x     = (const float*)d_in[0];
    const float* W     = (const float*)d_in[1];
    const float* att_s = (const float*)d_in[2];
    const float* att_d = (const float*)d_in[3];
    const float* bias  = (const float*)d_in[4];
    const float* w1    = (const float*)d_in[5];
    const float* b1    = (const float*)d_in[6];
    const float* w2    = (const float*)d_in[7];
    const float* b2    = (const float*)d_in[8];
    const void*  ei    = d_in[9];
    const void*  batch = d_in[10];
    float* out = (float*)d_out;

    k_detect<<<128, 256>>>((const uint4*)ei);
    k_wprep<<<(KDIM * HC / 4 + 255) / 256, 256>>>(W);
    k_deg<<<(EE / 2 + 255) / 256, 256>>>(ei);
    k_gemm_tc<<<(NN + BM - 1) / BM, 256>>>(x, att_s, att_d);   // profile slot 4
    int scan_blks = (NN + 1023) / 1024;
    k_scan1<<<scan_blks, 1024>>>();
    k_scan3<<<(NN + 255) / 256, 256>>>(scan_blks);
    k_edge<<<(ENQ + 255) / 256, 256>>>(ei);
    k_agg<<<(NN + 7) / 8, 256>>>(batch, bias);
    k_mlp<<<GGR, 64>>>(w1, b1, w2, b2, out);
}

// round 14
// speedup vs baseline: 1.1216x; 1.0286x over previous
#include <cuda_runtime.h>
#include <cuda_bf16.h>

// Problem constants (fixed by the reference)
#define NN 100000
#define EE 1600000
#define ENQ 1700000        // EE + NN (edges + self loops)
#define GGR 128
#define KDIM 329
#define HC 256             // H*C = 4*64

// GEMM tiling: single pass over all 256 columns
#define BM 64
#define BN 256
#define BK 32
#define NIT ((KDIM + BK - 1) / BK)   // 11

// int32-vs-int64 detection prefix (int64 entries checked)
#define DETN 131072

// ---------------- static device scratch (no cudaMalloc allowed) ----------------
__device__ __nv_bfloat162 d_xpb[(size_t)NN * HC / 2]; // [N, H*C] projected feats, bf16
__device__ __nv_bfloat16  d_Wb[KDIM * HC];            // W in bf16 (k_wprep)
__device__ float4 d_asrc[NN];             // a_src[n][4]
__device__ float4 d_adst[NN];             // a_dst[n][4]
__device__ uint4  d_slot[ENQ];            // CSR slot: {src, ex01(bf16x2), ex23(bf16x2), 0}
__device__ int    d_deg[NN];              // zero at rest; reset by k_scan1
__device__ int    d_rowptr[NN + 1];       // rebuilt every run by scans
__device__ int    d_bsum[128];
__device__ float  d_gsum[GGR * 64];       // zero at rest; reset by k_mlp
__device__ int    d_gcnt[GGR];            // zero at rest; reset by k_mlp
__device__ int    d_flag32;               // 1 if int32 inputs; reset by k_mlp

// ---------------- helpers ----------------
__device__ __forceinline__ int2 edge_sd(const void* ei, int e) {
    if (d_flag32) {
        const int* p = (const int*)ei;
        return make_int2(p[e], p[EE + e]);
    } else {
        const long long* p = (const long long*)ei;
        return make_int2((int)p[e], (int)p[EE + e]);
    }
}
__device__ __forceinline__ int batch_of(const void* b, int n) {
    if (d_flag32) return ((const int*)b)[n];
    return (int)((const long long*)b)[n];
}
__device__ __forceinline__ float lrelu(float v) { return v > 0.f ? v : 0.2f * v; }
__device__ __forceinline__ float2 bf2f(__nv_bfloat162 v) { return __bfloat1622float2(v); }
__device__ __forceinline__ unsigned packbf(float a, float b) {
    __nv_bfloat162 p = __float22bfloat162_rn(make_float2(a, b));
    return *(unsigned*)&p;
}
// FMA-only exp: range-reduce base-2, degree-5 Taylor on t = f*ln2 in [0, ln2),
// exponent spliced via integer add on the bit pattern. rel err ~8e-5 --
// far below the bf16 quantization (4e-3) already applied to ex.
__device__ __forceinline__ float fexp(float v) {
    float z = v * 1.4426950408889634f;          // x * log2(e)
    float zi = floorf(z);
    float t = (z - zi) * 0.6931471805599453f;   // residual back in e-base
    float p = 8.3333337e-3f;                    // 1/120
    p = p * t + 4.1666668e-2f;                  // 1/24
    p = p * t + 1.6666667e-1f;                  // 1/6
    p = p * t + 5.0e-1f;
    p = p * t + 1.0f;
    p = p * t + 1.0f;
    return __int_as_float(__float_as_int(p) + ((int)zi << 23));
}
__device__ __forceinline__ void cpa16(unsigned dst, const void* src, bool p) {
    int sz = p ? 16 : 0;
    asm volatile("cp.async.cg.shared.global [%0], [%1], 16, %2;\n"
                 :: "r"(dst), "l"(src), "r"(sz));
}
__device__ __forceinline__ void ldsm_x4(unsigned& r0, unsigned& r1, unsigned& r2, unsigned& r3,
                                        unsigned addr) {
    asm volatile("ldmatrix.sync.aligned.m8n8.x4.shared.b16 {%0,%1,%2,%3}, [%4];"
                 : "=r"(r0), "=r"(r1), "=r"(r2), "=r"(r3) : "r"(addr));
}
__device__ __forceinline__ void ldsm_x4t(unsigned& r0, unsigned& r1, unsigned& r2, unsigned& r3,
                                         unsigned addr) {
    asm volatile("ldmatrix.sync.aligned.m8n8.x4.trans.shared.b16 {%0,%1,%2,%3}, [%4];"
                 : "=r"(r0), "=r"(r1), "=r"(r2), "=r"(r3) : "r"(addr));
}
__device__ __forceinline__ void mma_bf16(float4& d,
                                         unsigned a0, unsigned a1, unsigned a2, unsigned a3,
                                         unsigned b0, unsigned b1) {
    asm volatile(
        "mma.sync.aligned.m16n8k16.row.col.f32.bf16.bf16.f32 "
        "{%0,%1,%2,%3}, {%4,%5,%6,%7}, {%8,%9}, {%0,%1,%2,%3};\n"
        : "+f"(d.x), "+f"(d.y), "+f"(d.z), "+f"(d.w)
        : "r"(a0), "r"(a1), "r"(a2), "r"(a3), "r"(b0), "r"(b1));
}

// ---------------- kernels ----------------
// Detect int32 vs int64 on a 128K-entry prefix: int64 LE hi words are all 0;
// int32 data there would be random node ids (P(all zero) ~ 0).
__global__ void k_detect(const uint4* __restrict__ ei) {
    int i = blockIdx.x * blockDim.x + threadIdx.x;
    bool nz = false;
    for (int q = i; q < DETN / 2; q += gridDim.x * blockDim.x) {
        uint4 v = ei[q];
        nz |= (v.y | v.w) != 0u;
    }
    unsigned b = __ballot_sync(0xffffffffu, nz);
    if ((threadIdx.x & 31) == 0 && b) atomicOr(&d_flag32, 1);
}

// W fp32 -> bf16.
__global__ void k_wprep(const float* __restrict__ W) {
    int i = blockIdx.x * 256 + threadIdx.x;          // float4 groups
    if (i * 4 < KDIM * HC) {
        float4 v = ((const float4*)W)[i];
        *(uint2*)&d_Wb[i * 4] = make_uint2(packbf(v.x, v.y), packbf(v.z, v.w));
    }
}

// Degree histogram, 2 edges/thread (EE even -> pairs aligned & in-bounds).
__global__ void k_deg(const void* __restrict__ ei) {
    int e = (blockIdx.x * blockDim.x + threadIdx.x) * 2;
    if (e >= EE) return;
    int d0, d1;
    if (d_flag32) {
        int2 dv = *(const int2*)((const int*)ei + EE + e);
        d0 = dv.x; d1 = dv.y;
    } else {
        longlong2 dv = *(const longlong2*)((const long long*)ei + EE + e);
        d0 = (int)dv.x; d1 = (int)dv.y;
    }
    atomicAdd(&d_deg[d0], 1);
    atomicAdd(&d_deg[d1], 1);
}

// Tensor-core GEMM: xp = x @ W via bf16 mma.m16n8k16 + ldmatrix.
// A: scalar LDG (x rows only 4B-aligned) -> pack -> STS.64.
// B: cp.async 16B direct from pre-converted d_Wb.
// Attention dots fused in the epilogue. Block 64x256, 8 warps (2M x 4N).
__global__ void __launch_bounds__(256) k_gemm_tc(const float* __restrict__ x,
                                                 const float* __restrict__ att_s,
                                                 const float* __restrict__ att_d) {
    __shared__ __align__(16) __nv_bfloat16 As[2][BM][BK + 8];   // row 80B
    __shared__ __align__(16) __nv_bfloat16 Bs[2][BK][BN + 8];   // row 528B
    __shared__ float sAtt[2][HC];
    const int tid = threadIdx.x;
    const int lane = tid & 31, wid = tid >> 5;
    const int wm = (wid & 1) * 32;
    const int wn = (wid >> 1) * 64;
    const int hd = wid >> 1;                       // head of this warp's col slice
    const int gid = lane >> 2, tig = lane & 3;
    const int row0 = blockIdx.x * BM;

    sAtt[0][tid] = att_s[tid];
    sAtt[1][tid] = att_d[tid];

    // A staging: lane g = tid&7 owns k in [4g, 4g+4); row rA = tid>>3 (+32 for h=1).
    const int g = tid & 7, rA = tid >> 3;
    bool rokh[2]; const float* pxh[2];
#pragma unroll
    for (int h = 0; h < 2; h++) {
        int gr = row0 + rA + 32 * h;
        rokh[h] = (gr < NN);
        pxh[h] = x + (size_t)(rokh[h] ? gr : 0) * KDIM;
    }

    float aF[2][4];
    float4 acc[2][8];
#pragma unroll
    for (int i = 0; i < 2; i++)
#pragma unroll
        for (int j = 0; j < 8; j++) acc[i][j] = make_float4(0.f, 0.f, 0.f, 0.f);

#define LDGA(k0)                                                                \
    {                                                                           \
        _Pragma("unroll")                                                       \
        for (int h = 0; h < 2; h++)                                             \
        _Pragma("unroll")                                                       \
        for (int q = 0; q < 4; q++) {                                           \
            int k = (k0) + 4 * g + q;                                           \
            aF[h][q] = (rokh[h] && k < KDIM) ? __ldg(pxh[h] + k) : 0.f;         \
        }                                                                       \
    }
#define STSA(st)                                                                \
    {                                                                           \
        _Pragma("unroll")                                                       \
        for (int h = 0; h < 2; h++)                                             \
            *(uint2*)&As[st][rA + 32 * h][4 * g] =                              \
                make_uint2(packbf(aF[h][0], aF[h][1]), packbf(aF[h][2], aF[h][3])); \
    }
#define LDB_CPA(st, k0)                                                         \
    {                                                                           \
        _Pragma("unroll")                                                       \
        for (int q = 0; q < 4; q++) {                                           \
            int c = tid + 256 * q;                                              \
            int brow = c >> 5, bcol = (c & 31) * 8;                             \
            int gk = (k0) + brow;                                               \
            bool p = (gk < KDIM);                                               \
            unsigned db = (unsigned)__cvta_generic_to_shared(&Bs[st][brow][bcol]); \
            cpa16(db, d_Wb + (size_t)(p ? gk : 0) * HC + bcol, p);              \
        }                                                                       \
        asm volatile("cp.async.commit_group;\n");                               \
    }

    LDGA(0)
    LDB_CPA(0, 0)
    STSA(0)
    asm volatile("cp.async.wait_group 0;\n");
    __syncthreads();

    for (int it = 0; it < NIT; it++) {
        const int s = it & 1;
        if (it + 1 < NIT) {
            LDGA((it + 1) * BK)
            LDB_CPA(s ^ 1, (it + 1) * BK)      // async into the idle buffer
        }

#pragma unroll
        for (int kk = 0; kk < BK; kk += 16) {
            unsigned a[2][4], bq[4][4];
#pragma unroll
            for (int i = 0; i < 2; i++) {
                unsigned ad = (unsigned)__cvta_generic_to_shared(
                    &As[s][wm + i * 16 + (lane & 15)][kk + (lane >> 4) * 8]);
                ldsm_x4(a[i][0], a[i][1], a[i][2], a[i][3], ad);
            }
#pragma unroll
            for (int j = 0; j < 4; j++) {
                unsigned ad = (unsigned)__cvta_generic_to_shared(
                    &Bs[s][kk + (lane & 15)][wn + j * 16 + (lane >> 4) * 8]);
                ldsm_x4t(bq[j][0], bq[j][1], bq[j][2], bq[j][3], ad);
            }
#pragma unroll
            for (int i = 0; i < 2; i++)
#pragma unroll
                for (int j = 0; j < 4; j++) {
                    mma_bf16(acc[i][2 * j], a[i][0], a[i][1], a[i][2], a[i][3],
                             bq[j][0], bq[j][1]);
                    mma_bf16(acc[i][2 * j + 1], a[i][0], a[i][1], a[i][2], a[i][3],
                             bq[j][2], bq[j][3]);
                }
        }

        if (it + 1 < NIT) {
            STSA(s ^ 1)                        // s^1 readers done before last sync
            asm volatile("cp.async.wait_group 0;\n");
            __syncthreads();
        }
    }
#undef LDGA
#undef STSA
#undef LDB_CPA

    // Epilogue: bf16x2 stores + fused attention dots (fp32 accumulators).
    float psA[2] = {0.f, 0.f}, pdA[2] = {0.f, 0.f};
    float psB[2] = {0.f, 0.f}, pdB[2] = {0.f, 0.f};
#pragma unroll
    for (int i = 0; i < 2; i++) {
        int r0 = row0 + wm + i * 16 + gid;
#pragma unroll
        for (int j = 0; j < 8; j++) {
            int c = wn + j * 8 + tig * 2;
            float avs0 = sAtt[0][c], avs1 = sAtt[0][c + 1];
            float avd0 = sAtt[1][c], avd1 = sAtt[1][c + 1];
            psA[i] += acc[i][j].x * avs0 + acc[i][j].y * avs1;
            pdA[i] += acc[i][j].x * avd0 + acc[i][j].y * avd1;
            psB[i] += acc[i][j].z * avs0 + acc[i][j].w * avs1;
            pdB[i] += acc[i][j].z * avd0 + acc[i][j].w * avd1;
            if (r0 < NN)
                d_xpb[((size_t)r0 * HC + c) >> 1] =
                    __float22bfloat162_rn(make_float2(acc[i][j].x, acc[i][j].y));
            if (r0 + 8 < NN)
                d_xpb[((size_t)(r0 + 8) * HC + c) >> 1] =
                    __float22bfloat162_rn(make_float2(acc[i][j].z, acc[i][j].w));
        }
    }
#pragma unroll
    for (int i = 0; i < 2; i++) {
        psA[i] += __shfl_xor_sync(0xffffffffu, psA[i], 1);
        psA[i] += __shfl_xor_sync(0xffffffffu, psA[i], 2);
        pdA[i] += __shfl_xor_sync(0xffffffffu, pdA[i], 1);
        pdA[i] += __shfl_xor_sync(0xffffffffu, pdA[i], 2);
        psB[i] += __shfl_xor_sync(0xffffffffu, psB[i], 1);
        psB[i] += __shfl_xor_sync(0xffffffffu, psB[i], 2);
        pdB[i] += __shfl_xor_sync(0xffffffffu, pdB[i], 1);
        pdB[i] += __shfl_xor_sync(0xffffffffu, pdB[i], 2);
        if (tig == 0) {
            int r0 = row0 + wm + i * 16 + gid;
            if (r0 < NN) {
                ((float*)&d_asrc[r0])[hd] = psA[i];
                ((float*)&d_adst[r0])[hd] = pdA[i];
            }
            if (r0 + 8 < NN) {
                ((float*)&d_asrc[r0 + 8])[hd] = psB[i];
                ((float*)&d_adst[r0 + 8])[hd] = pdB[i];
            }
        }
    }
}

// Exclusive scan of (deg+1) -> rowptr phase 1; resets d_deg for next run.
__global__ void __launch_bounds__(1024) k_scan1() {
    __shared__ int sh[1024];
    int i = blockIdx.x * 1024 + threadIdx.x;
    int v = 0;
    if (i < NN) {
        v = d_deg[i] + 1;          // +1 = self loop
        d_deg[i] = 0;              // consumer-reset
    }
    sh[threadIdx.x] = v;
    __syncthreads();
    for (int off = 1; off < 1024; off <<= 1) {
        int t = 0;
        if (threadIdx.x >= off) t = sh[threadIdx.x - off];
        __syncthreads();
        sh[threadIdx.x] += t;
        __syncthreads();
    }
    if (i < NN) d_rowptr[i] = sh[threadIdx.x] - v;
    if (threadIdx.x == 1023) d_bsum[blockIdx.x] = sh[1023];
}

// Phase 2+3 merged: every block redundantly prefix-sums the block sums in smem,
// then applies its offset.
__global__ void k_scan3(int nblk) {
    __shared__ int sb[128];
    if (threadIdx.x < nblk) sb[threadIdx.x] = d_bsum[threadIdx.x];
    __syncthreads();
    if (threadIdx.x == 0) {
        int run = 0;
        for (int b = 0; b < nblk; b++) { int t = sb[b]; sb[b] = run; run += t; }
    }
    __syncthreads();
    int i = blockIdx.x * blockDim.x + threadIdx.x;
    if (i < NN) d_rowptr[i] += sb[i >> 10];
    if (i == 0) d_rowptr[NN] = ENQ;
}

// Single edge pass (1 edge/thread): ex = fexp(leaky(logit)) on the FMA pipe
// (no MUFU); scatter packed {src, ex(bf16x4)} with ONE 16B store and ONE
// atomic (on d_rowptr[d] itself; post-pass rowptr[n] == original rowptr[n+1]).
// (segment-max skipped: logits O(1), exp cannot overflow; softmax identical.)
__global__ void k_edge(const void* __restrict__ ei) {
    int e = blockIdx.x * blockDim.x + threadIdx.x;
    if (e >= ENQ) return;
    int s, d;
    if (e < EE) { int2 sd = edge_sd(ei, e); s = sd.x; d = sd.y; }
    else { s = d = e - EE; }
    float4 as = d_asrc[s], ad = d_adst[d];
    float ex0 = fexp(lrelu(as.x + ad.x));
    float ex1 = fexp(lrelu(as.y + ad.y));
    float ex2 = fexp(lrelu(as.z + ad.z));
    float ex3 = fexp(lrelu(as.w + ad.w));
    int slot = atomicAdd(&d_rowptr[d], 1);
    uint4 sl;
    sl.x = (unsigned)s;
    sl.y = packbf(ex0, ex1);
    sl.z = packbf(ex2, ex3);
    sl.w = 0u;
    d_slot[slot] = sl;
}

// Per-node aggregation (measured best): ONE WARP per node; lane owns bf16x2
// column pair per head. Slot loads warp-uniform; xp gathers coalesced.
// 2-way unroll; local denominator; divide once at the end.
__global__ void __launch_bounds__(256) k_agg(const void* __restrict__ batch,
                                             const float* __restrict__ bias) {
    int n = blockIdx.x * 8 + (threadIdx.x >> 5);
    int lane = threadIdx.x & 31;
    if (n >= NN) return;
    int beg = (n == 0) ? 0 : d_rowptr[n - 1];
    int end = d_rowptr[n];
    float2 a0 = {0.f, 0.f}, a1 = {0.f, 0.f}, a2 = {0.f, 0.f}, a3 = {0.f, 0.f};
    float dn0 = 0.f, dn1 = 0.f, dn2 = 0.f, dn3 = 0.f;
    int i = beg;
    for (; i + 2 <= end; i += 2) {
        uint4 slA = d_slot[i];
        uint4 slB = d_slot[i + 1];
        const __nv_bfloat162* xrA = &d_xpb[(size_t)(int)slA.x * HC / 2];
        const __nv_bfloat162* xrB = &d_xpb[(size_t)(int)slB.x * HC / 2];
        float2 uA0 = bf2f(xrA[lane]),      uB0 = bf2f(xrB[lane]);
        float2 uA1 = bf2f(xrA[32 + lane]), uB1 = bf2f(xrB[32 + lane]);
        float2 uA2 = bf2f(xrA[64 + lane]), uB2 = bf2f(xrB[64 + lane]);
        float2 uA3 = bf2f(xrA[96 + lane]), uB3 = bf2f(xrB[96 + lane]);
        float2 eA01 = bf2f(*(__nv_bfloat162*)&slA.y);
        float2 eA23 = bf2f(*(__nv_bfloat162*)&slA.z);
        float2 eB01 = bf2f(*(__nv_bfloat162*)&slB.y);
        float2 eB23 = bf2f(*(__nv_bfloat162*)&slB.z);
        dn0 += eA01.x + eB01.x; dn1 += eA01.y + eB01.y;
        dn2 += eA23.x + eB23.x; dn3 += eA23.y + eB23.y;
        a0.x += eA01.x * uA0.x + eB01.x * uB0.x; a0.y += eA01.x * uA0.y + eB01.x * uB0.y;
        a1.x += eA01.y * uA1.x + eB01.y * uB1.x; a1.y += eA01.y * uA1.y + eB01.y * uB1.y;
        a2.x += eA23.x * uA2.x + eB23.x * uB2.x; a2.y += eA23.x * uA2.y + eB23.x * uB2.y;
        a3.x += eA23.y * uA3.x + eB23.y * uB3.x; a3.y += eA23.y * uA3.y + eB23.y * uB3.y;
    }
    if (i < end) {
        uint4 sl = d_slot[i];
        const __nv_bfloat162* xr = &d_xpb[(size_t)(int)sl.x * HC / 2];
        float2 al01 = bf2f(*(__nv_bfloat162*)&sl.y);
        float2 al23 = bf2f(*(__nv_bfloat162*)&sl.z);
        dn0 += al01.x; dn1 += al01.y; dn2 += al23.x; dn3 += al23.y;
        float2 v0 = bf2f(xr[lane]);
        float2 v1 = bf2f(xr[32 + lane]);
        float2 v2 = bf2f(xr[64 + lane]);
        float2 v3 = bf2f(xr[96 + lane]);
        a0.x += al01.x * v0.x; a0.y += al01.x * v0.y;
        a1.x += al01.y * v1.x; a1.y += al01.y * v1.y;
        a2.x += al23.x * v2.x; a2.y += al23.x * v2.y;
        a3.x += al23.y * v3.x; a3.y += al23.y * v3.y;
    }
    float2 bv = ((const float2*)bias)[lane];
    float hv0 = 0.25f * (a0.x / dn0 + a1.x / dn1 + a2.x / dn2 + a3.x / dn3) + bv.x;
    float hv1 = 0.25f * (a0.y / dn0 + a1.y / dn1 + a2.y / dn2 + a3.y / dn3) + bv.y;
    hv0 = fmaxf(hv0, 0.f);
    hv1 = fmaxf(hv1, 0.f);
    int g = batch_of(batch, n);
    atomicAdd(&d_gsum[g * 64 + 2 * lane], hv0);
    atomicAdd(&d_gsum[g * 64 + 2 * lane + 1], hv1);
    if (lane == 0) atomicAdd(&d_gcnt[g], 1);
}

// Head MLP: one block per graph. Also consumer-resets gsum/gcnt/flag32.
__global__ void k_mlp(const float* __restrict__ w1, const float* __restrict__ b1,
                      const float* __restrict__ w2, const float* __restrict__ b2,
                      float* __restrict__ out) {
    __shared__ float sg[64], sz[64];
    int g = blockIdx.x, c = threadIdx.x;
    float cnt = (float)d_gcnt[g];
    if (cnt < 1.f) cnt = 1.f;
    sg[c] = d_gsum[g * 64 + c] / cnt;
    __syncthreads();
    d_gsum[g * 64 + c] = 0.f;                 // consumer-reset
    if (c == 0) d_gcnt[g] = 0;
    if (g == 0 && c == 0) d_flag32 = 0;
    float z = b1[c];
#pragma unroll 16
    for (int k = 0; k < 64; k++) z += sg[k] * w1[k * 64 + c];
    z = fmaxf(z, 0.f);
    sz[c] = z * w2[c];
    __syncthreads();
    if (c < 32) {
        float v = sz[c] + sz[c + 32];
#pragma unroll
        for (int o = 16; o; o >>= 1) v += __shfl_down_sync(0xffffffffu, v, o);
        if (c == 0) out[g] = 1.f / (1.f + expf(-(v + b2[0])));
    }
}

// ---------------- launcher ----------------
extern "C" void kernel_launch(void* const* d_in, const int* in_sizes, int n_in,
                              void* d_out, int out_size) {
    const float* x     = (const float*)d_in[0];
    const float* W     = (const float*)d_in[1];
    const float* att_s = (const float*)d_in[2];
    const float* att_d = (const float*)d_in[3];
    const float* bias  = (const float*)d_in[4];
    const float* w1    = (const float*)d_in[5];
    const float* b1    = (const float*)d_in[6];
    const float* w2    = (const float*)d_in[7];
    const float* b2    = (const float*)d_in[8];
    const void*  ei    = d_in[9];
    const void*  batch = d_in[10];
    float* out = (float*)d_out;

    k_detect<<<64, 256>>>((const uint4*)ei);
    k_wprep<<<(KDIM * HC / 4 + 255) / 256, 256>>>(W);
    k_deg<<<(EE / 2 + 255) / 256, 256>>>(ei);
    k_gemm_tc<<<(NN + BM - 1) / BM, 256>>>(x, att_s, att_d);   // profile slot 4
    int scan_blks = (NN + 1023) / 1024;
    k_scan1<<<scan_blks, 1024>>>();
    k_scan3<<<(NN + 255) / 256, 256>>>(scan_blks);
    k_edge<<<(ENQ + 255) / 256, 256>>>(ei);
    k_agg<<<(NN + 7) / 8, 256>>>(batch, bias);
    k_mlp<<<GGR, 64>>>(w1, b1, w2, b2, out);
}

// round 16
// speedup vs baseline: 1.5216x; 1.3567x over previous
#include <cuda_runtime.h>
#include <cuda_bf16.h>

// Problem constants (fixed by the reference)
#define NN 100000
#define EE 1600000
#define ENQ 1700000        // EE + NN (edges + self loops)
#define GGR 128
#define KDIM 329
#define HC 256             // H*C = 4*64

// GEMM tiling: single pass over all 256 columns
#define BM 64
#define BN 256
#define BK 32
#define NIT ((KDIM + BK - 1) / BK)   // 11

// int32-vs-int64 detection prefix (int64 entries checked)
#define DETN 131072

// ---------------- static device scratch (no cudaMalloc allowed) ----------------
__device__ __nv_bfloat162 d_xpb[(size_t)NN * HC / 2]; // [N, H*C] projected feats, bf16
__device__ __nv_bfloat16  d_Wb[KDIM * HC];            // W in bf16 (k_wprep)
__device__ float4 d_asrc[NN];             // a_src[n][4]
__device__ float4 d_adst[NN];             // a_dst[n][4]
__device__ uint4  d_slot[ENQ];            // CSR slot: {src, ex01(bf16x2), ex23(bf16x2), 0}
__device__ int    d_deg[NN];              // zero at rest; reset by k_scan1
__device__ int    d_rowptr[NN + 1];       // rebuilt every run by scans
__device__ int    d_bsum[128];
__device__ float  d_gsum[GGR * 64];       // zero at rest; reset by k_mlp
__device__ int    d_gcnt[GGR];            // zero at rest; reset by k_mlp
__device__ int    d_flag32;               // 1 if int32 inputs; reset by k_mlp

// ---------------- helpers ----------------
__device__ __forceinline__ int2 edge_sd(const void* ei, int e) {
    if (d_flag32) {
        const int* p = (const int*)ei;
        return make_int2(p[e], p[EE + e]);
    } else {
        const long long* p = (const long long*)ei;
        return make_int2((int)p[e], (int)p[EE + e]);
    }
}
__device__ __forceinline__ int batch_of(const void* b, int n) {
    if (d_flag32) return ((const int*)b)[n];
    return (int)((const long long*)b)[n];
}
__device__ __forceinline__ float lrelu(float v) { return v > 0.f ? v : 0.2f * v; }
__device__ __forceinline__ float2 bf2f(__nv_bfloat162 v) { return __bfloat1622float2(v); }
__device__ __forceinline__ unsigned packbf(float a, float b) {
    __nv_bfloat162 p = __float22bfloat162_rn(make_float2(a, b));
    return *(unsigned*)&p;
}
// FMA-only exp: range-reduce base-2, degree-5 Taylor on t = f*ln2 in [0, ln2),
// exponent spliced via integer add on the bit pattern. rel err ~8e-5 --
// far below the bf16 quantization (4e-3) already applied to ex.
__device__ __forceinline__ float fexp(float v) {
    float z = v * 1.4426950408889634f;          // x * log2(e)
    float zi = floorf(z);
    float t = (z - zi) * 0.6931471805599453f;   // residual back in e-base
    float p = 8.3333337e-3f;                    // 1/120
    p = p * t + 4.1666668e-2f;                  // 1/24
    p = p * t + 1.6666667e-1f;                  // 1/6
    p = p * t + 5.0e-1f;
    p = p * t + 1.0f;
    p = p * t + 1.0f;
    return __int_as_float(__float_as_int(p) + ((int)zi << 23));
}
__device__ __forceinline__ void cpa16(unsigned dst, const void* src, bool p) {
    int sz = p ? 16 : 0;
    asm volatile("cp.async.cg.shared.global [%0], [%1], 16, %2;\n"
                 :: "r"(dst), "l"(src), "r"(sz));
}
__device__ __forceinline__ void ldsm_x4(unsigned& r0, unsigned& r1, unsigned& r2, unsigned& r3,
                                        unsigned addr) {
    asm volatile("ldmatrix.sync.aligned.m8n8.x4.shared.b16 {%0,%1,%2,%3}, [%4];"
                 : "=r"(r0), "=r"(r1), "=r"(r2), "=r"(r3) : "r"(addr));
}
__device__ __forceinline__ void ldsm_x4t(unsigned& r0, unsigned& r1, unsigned& r2, unsigned& r3,
                                         unsigned addr) {
    asm volatile("ldmatrix.sync.aligned.m8n8.x4.trans.shared.b16 {%0,%1,%2,%3}, [%4];"
                 : "=r"(r0), "=r"(r1), "=r"(r2), "=r"(r3) : "r"(addr));
}
__device__ __forceinline__ void mma_bf16(float4& d,
                                         unsigned a0, unsigned a1, unsigned a2, unsigned a3,
                                         unsigned b0, unsigned b1) {
    asm volatile(
        "mma.sync.aligned.m16n8k16.row.col.f32.bf16.bf16.f32 "
        "{%0,%1,%2,%3}, {%4,%5,%6,%7}, {%8,%9}, {%0,%1,%2,%3};\n"
        : "+f"(d.x), "+f"(d.y), "+f"(d.z), "+f"(d.w)
        : "r"(a0), "r"(a1), "r"(a2), "r"(a3), "r"(b0), "r"(b1));
}

// ---------------- kernels ----------------
// Detect int32 vs int64 on a 128K-entry prefix: int64 LE hi words are all 0;
// int32 data there would be random node ids (P(all zero) ~ 0).
__global__ void k_detect(const uint4* __restrict__ ei) {
    int i = blockIdx.x * blockDim.x + threadIdx.x;
    bool nz = false;
    for (int q = i; q < DETN / 2; q += gridDim.x * blockDim.x) {
        uint4 v = ei[q];
        nz |= (v.y | v.w) != 0u;
    }
    unsigned b = __ballot_sync(0xffffffffu, nz);
    if ((threadIdx.x & 31) == 0 && b) atomicOr(&d_flag32, 1);
}

// W fp32 -> bf16.
__global__ void k_wprep(const float* __restrict__ W) {
    int i = blockIdx.x * 256 + threadIdx.x;          // float4 groups
    if (i * 4 < KDIM * HC) {
        float4 v = ((const float4*)W)[i];
        *(uint2*)&d_Wb[i * 4] = make_uint2(packbf(v.x, v.y), packbf(v.z, v.w));
    }
}

// Degree histogram, 2 edges/thread (EE even -> pairs aligned & in-bounds).
__global__ void k_deg(const void* __restrict__ ei) {
    int e = (blockIdx.x * blockDim.x + threadIdx.x) * 2;
    if (e >= EE) return;
    int d0, d1;
    if (d_flag32) {
        int2 dv = *(const int2*)((const int*)ei + EE + e);
        d0 = dv.x; d1 = dv.y;
    } else {
        longlong2 dv = *(const longlong2*)((const long long*)ei + EE + e);
        d0 = (int)dv.x; d1 = (int)dv.y;
    }
    atomicAdd(&d_deg[d0], 1);
    atomicAdd(&d_deg[d1], 1);
}

// Tensor-core GEMM: xp = x @ W via bf16 mma.m16n8k16 + ldmatrix.
// A: scalar LDG (x rows only 4B-aligned) -> pack -> STS.64.
// B: cp.async 16B direct from pre-converted d_Wb.
// Attention dots fused in the epilogue. Block 64x256, 8 warps (2M x 4N).
__global__ void __launch_bounds__(256) k_gemm_tc(const float* __restrict__ x,
                                                 const float* __restrict__ att_s,
                                                 const float* __restrict__ att_d) {
    __shared__ __align__(16) __nv_bfloat16 As[2][BM][BK + 8];   // row 80B
    __shared__ __align__(16) __nv_bfloat16 Bs[2][BK][BN + 8];   // row 528B
    __shared__ float sAtt[2][HC];
    const int tid = threadIdx.x;
    const int lane = tid & 31, wid = tid >> 5;
    const int wm = (wid & 1) * 32;
    const int wn = (wid >> 1) * 64;
    const int hd = wid >> 1;                       // head of this warp's col slice
    const int gid = lane >> 2, tig = lane & 3;
    const int row0 = blockIdx.x * BM;

    sAtt[0][tid] = att_s[tid];
    sAtt[1][tid] = att_d[tid];

    // A staging: lane g = tid&7 owns k in [4g, 4g+4); row rA = tid>>3 (+32 for h=1).
    const int g = tid & 7, rA = tid >> 3;
    bool rokh[2]; const float* pxh[2];
#pragma unroll
    for (int h = 0; h < 2; h++) {
        int gr = row0 + rA + 32 * h;
        rokh[h] = (gr < NN);
        pxh[h] = x + (size_t)(rokh[h] ? gr : 0) * KDIM;
    }

    float aF[2][4];
    float4 acc[2][8];
#pragma unroll
    for (int i = 0; i < 2; i++)
#pragma unroll
        for (int j = 0; j < 8; j++) acc[i][j] = make_float4(0.f, 0.f, 0.f, 0.f);

#define LDGA(k0)                                                                \
    {                                                                           \
        _Pragma("unroll")                                                       \
        for (int h = 0; h < 2; h++)                                             \
        _Pragma("unroll")                                                       \
        for (int q = 0; q < 4; q++) {                                           \
            int k = (k0) + 4 * g + q;                                           \
            aF[h][q] = (rokh[h] && k < KDIM) ? __ldg(pxh[h] + k) : 0.f;         \
        }                                                                       \
    }
#define STSA(st)                                                                \
    {                                                                           \
        _Pragma("unroll")                                                       \
        for (int h = 0; h < 2; h++)                                             \
            *(uint2*)&As[st][rA + 32 * h][4 * g] =                              \
                make_uint2(packbf(aF[h][0], aF[h][1]), packbf(aF[h][2], aF[h][3])); \
    }
#define LDB_CPA(st, k0)                                                         \
    {                                                                           \
        _Pragma("unroll")                                                       \
        for (int q = 0; q < 4; q++) {                                           \
            int c = tid + 256 * q;                                              \
            int brow = c >> 5, bcol = (c & 31) * 8;                             \
            int gk = (k0) + brow;                                               \
            bool p = (gk < KDIM);                                               \
            unsigned db = (unsigned)__cvta_generic_to_shared(&Bs[st][brow][bcol]); \
            cpa16(db, d_Wb + (size_t)(p ? gk : 0) * HC + bcol, p);              \
        }                                                                       \
        asm volatile("cp.async.commit_group;\n");                               \
    }

    LDGA(0)
    LDB_CPA(0, 0)
    STSA(0)
    asm volatile("cp.async.wait_group 0;\n");
    __syncthreads();

    for (int it = 0; it < NIT; it++) {
        const int s = it & 1;
        if (it + 1 < NIT) {
            LDGA((it + 1) * BK)
            LDB_CPA(s ^ 1, (it + 1) * BK)      // async into the idle buffer
        }

#pragma unroll
        for (int kk = 0; kk < BK; kk += 16) {
            unsigned a[2][4], bq[4][4];
#pragma unroll
            for (int i = 0; i < 2; i++) {
                unsigned ad = (unsigned)__cvta_generic_to_shared(
                    &As[s][wm + i * 16 + (lane & 15)][kk + (lane >> 4) * 8]);
                ldsm_x4(a[i][0], a[i][1], a[i][2], a[i][3], ad);
            }
#pragma unroll
            for (int j = 0; j < 4; j++) {
                unsigned ad = (unsigned)__cvta_generic_to_shared(
                    &Bs[s][kk + (lane & 15)][wn + j * 16 + (lane >> 4) * 8]);
                ldsm_x4t(bq[j][0], bq[j][1], bq[j][2], bq[j][3], ad);
            }
#pragma unroll
            for (int i = 0; i < 2; i++)
#pragma unroll
                for (int j = 0; j < 4; j++) {
                    mma_bf16(acc[i][2 * j], a[i][0], a[i][1], a[i][2], a[i][3],
                             bq[j][0], bq[j][1]);
                    mma_bf16(acc[i][2 * j + 1], a[i][0], a[i][1], a[i][2], a[i][3],
                             bq[j][2], bq[j][3]);
                }
        }

        if (it + 1 < NIT) {
            STSA(s ^ 1)                        // s^1 readers done before last sync
            asm volatile("cp.async.wait_group 0;\n");
            __syncthreads();
        }
    }
#undef LDGA
#undef STSA
#undef LDB_CPA

    // Epilogue: bf16x2 stores + fused attention dots (fp32 accumulators).
    float psA[2] = {0.f, 0.f}, pdA[2] = {0.f, 0.f};
    float psB[2] = {0.f, 0.f}, pdB[2] = {0.f, 0.f};
#pragma unroll
    for (int i = 0; i < 2; i++) {
        int r0 = row0 + wm + i * 16 + gid;
#pragma unroll
        for (int j = 0; j < 8; j++) {
            int c = wn + j * 8 + tig * 2;
            float avs0 = sAtt[0][c], avs1 = sAtt[0][c + 1];
            float avd0 = sAtt[1][c], avd1 = sAtt[1][c + 1];
            psA[i] += acc[i][j].x * avs0 + acc[i][j].y * avs1;
            pdA[i] += acc[i][j].x * avd0 + acc[i][j].y * avd1;
            psB[i] += acc[i][j].z * avs0 + acc[i][j].w * avs1;
            pdB[i] += acc[i][j].z * avd0 + acc[i][j].w * avd1;
            if (r0 < NN)
                d_xpb[((size_t)r0 * HC + c) >> 1] =
                    __float22bfloat162_rn(make_float2(acc[i][j].x, acc[i][j].y));
            if (r0 + 8 < NN)
                d_xpb[((size_t)(r0 + 8) * HC + c) >> 1] =
                    __float22bfloat162_rn(make_float2(acc[i][j].z, acc[i][j].w));
        }
    }
#pragma unroll
    for (int i = 0; i < 2; i++) {
        psA[i] += __shfl_xor_sync(0xffffffffu, psA[i], 1);
        psA[i] += __shfl_xor_sync(0xffffffffu, psA[i], 2);
        pdA[i] += __shfl_xor_sync(0xffffffffu, pdA[i], 1);
        pdA[i] += __shfl_xor_sync(0xffffffffu, pdA[i], 2);
        psB[i] += __shfl_xor_sync(0xffffffffu, psB[i], 1);
        psB[i] += __shfl_xor_sync(0xffffffffu, psB[i], 2);
        pdB[i] += __shfl_xor_sync(0xffffffffu, pdB[i], 1);
        pdB[i] += __shfl_xor_sync(0xffffffffu, pdB[i], 2);
        if (tig == 0) {
            int r0 = row0 + wm + i * 16 + gid;
            if (r0 < NN) {
                ((float*)&d_asrc[r0])[hd] = psA[i];
                ((float*)&d_adst[r0])[hd] = pdA[i];
            }
            if (r0 + 8 < NN) {
                ((float*)&d_asrc[r0 + 8])[hd] = psB[i];
                ((float*)&d_adst[r0 + 8])[hd] = pdB[i];
            }
        }
    }
}

// Exclusive scan of (deg+1) -> rowptr phase 1; resets d_deg for next run.
__global__ void __launch_bounds__(1024) k_scan1() {
    __shared__ int sh[1024];
    int i = blockIdx.x * 1024 + threadIdx.x;
    int v = 0;
    if (i < NN) {
        v = d_deg[i] + 1;          // +1 = self loop
        d_deg[i] = 0;              // consumer-reset
    }
    sh[threadIdx.x] = v;
    __syncthreads();
    for (int off = 1; off < 1024; off <<= 1) {
        int t = 0;
        if (threadIdx.x >= off) t = sh[threadIdx.x - off];
        __syncthreads();
        sh[threadIdx.x] += t;
        __syncthreads();
    }
    if (i < NN) d_rowptr[i] = sh[threadIdx.x] - v;
    if (threadIdx.x == 1023) d_bsum[blockIdx.x] = sh[1023];
}

// Phase 2+3 merged: every block redundantly prefix-sums the block sums in smem,
// then applies its offset.
__global__ void k_scan3(int nblk) {
    __shared__ int sb[128];
    if (threadIdx.x < nblk) sb[threadIdx.x] = d_bsum[threadIdx.x];
    __syncthreads();
    if (threadIdx.x == 0) {
        int run = 0;
        for (int b = 0; b < nblk; b++) { int t = sb[b]; sb[b] = run; run += t; }
    }
    __syncthreads();
    int i = blockIdx.x * blockDim.x + threadIdx.x;
    if (i < NN) d_rowptr[i] += sb[i >> 10];
    if (i == 0) d_rowptr[NN] = ENQ;
}

// Single edge pass (1 edge/thread): ex = fexp(leaky(logit)) on the FMA pipe
// (no MUFU); scatter packed {src, ex(bf16x4)} with ONE 16B store and ONE
// atomic (on d_rowptr[d] itself; post-pass rowptr[n] == original rowptr[n+1]).
// (segment-max skipped: logits O(1), exp cannot overflow; softmax identical.)
__global__ void k_edge(const void* __restrict__ ei) {
    int e = blockIdx.x * blockDim.x + threadIdx.x;
    if (e >= ENQ) return;
    int s, d;
    if (e < EE) { int2 sd = edge_sd(ei, e); s = sd.x; d = sd.y; }
    else { s = d = e - EE; }
    float4 as = d_asrc[s], ad = d_adst[d];
    float ex0 = fexp(lrelu(as.x + ad.x));
    float ex1 = fexp(lrelu(as.y + ad.y));
    float ex2 = fexp(lrelu(as.z + ad.z));
    float ex3 = fexp(lrelu(as.w + ad.w));
    int slot = atomicAdd(&d_rowptr[d], 1);
    uint4 sl;
    sl.x = (unsigned)s;
    sl.y = packbf(ex0, ex1);
    sl.z = packbf(ex2, ex3);
    sl.w = 0u;
    d_slot[slot] = sl;
}

// Per-node aggregation: ONE WARP per node; lane owns bf16x2 column pair per
// head. NEW: block-level pre-reduction of the graph-pool contribution.
// batch is SORTED, so the block's 8 nodes share 1-2 graph ids; parking hv in
// smem and run-length merging by g cuts d_gsum atomics ~8x (6.4M -> ~0.9M),
// removing the same-address L2-atomic serialization.
__global__ void __launch_bounds__(256) k_agg(const void* __restrict__ batch,
                                             const float* __restrict__ bias) {
    __shared__ float sHv[8][64];
    __shared__ int   sG[8];
    int wid = threadIdx.x >> 5;
    int lane = threadIdx.x & 31;
    int n = blockIdx.x * 8 + wid;
    bool valid = (n < NN);

    if (valid) {
        int beg = (n == 0) ? 0 : d_rowptr[n - 1];
        int end = d_rowptr[n];
        float2 a0 = {0.f, 0.f}, a1 = {0.f, 0.f}, a2 = {0.f, 0.f}, a3 = {0.f, 0.f};
        float dn0 = 0.f, dn1 = 0.f, dn2 = 0.f, dn3 = 0.f;
        int i = beg;
        for (; i + 2 <= end; i += 2) {
            uint4 slA = d_slot[i];
            uint4 slB = d_slot[i + 1];
            const __nv_bfloat162* xrA = &d_xpb[(size_t)(int)slA.x * HC / 2];
            const __nv_bfloat162* xrB = &d_xpb[(size_t)(int)slB.x * HC / 2];
            float2 uA0 = bf2f(xrA[lane]),      uB0 = bf2f(xrB[lane]);
            float2 uA1 = bf2f(xrA[32 + lane]), uB1 = bf2f(xrB[32 + lane]);
            float2 uA2 = bf2f(xrA[64 + lane]), uB2 = bf2f(xrB[64 + lane]);
            float2 uA3 = bf2f(xrA[96 + lane]), uB3 = bf2f(xrB[96 + lane]);
            float2 eA01 = bf2f(*(__nv_bfloat162*)&slA.y);
            float2 eA23 = bf2f(*(__nv_bfloat162*)&slA.z);
            float2 eB01 = bf2f(*(__nv_bfloat162*)&slB.y);
            float2 eB23 = bf2f(*(__nv_bfloat162*)&slB.z);
            dn0 += eA01.x + eB01.x; dn1 += eA01.y + eB01.y;
            dn2 += eA23.x + eB23.x; dn3 += eA23.y + eB23.y;
            a0.x += eA01.x * uA0.x + eB01.x * uB0.x; a0.y += eA01.x * uA0.y + eB01.x * uB0.y;
            a1.x += eA01.y * uA1.x + eB01.y * uB1.x; a1.y += eA01.y * uA1.y + eB01.y * uB1.y;
            a2.x += eA23.x * uA2.x + eB23.x * uB2.x; a2.y += eA23.x * uA2.y + eB23.x * uB2.y;
            a3.x += eA23.y * uA3.x + eB23.y * uB3.x; a3.y += eA23.y * uA3.y + eB23.y * uB3.y;
        }
        if (i < end) {
            uint4 sl = d_slot[i];
            const __nv_bfloat162* xr = &d_xpb[(size_t)(int)sl.x * HC / 2];
            float2 al01 = bf2f(*(__nv_bfloat162*)&sl.y);
            float2 al23 = bf2f(*(__nv_bfloat162*)&sl.z);
            dn0 += al01.x; dn1 += al01.y; dn2 += al23.x; dn3 += al23.y;
            float2 v0 = bf2f(xr[lane]);
            float2 v1 = bf2f(xr[32 + lane]);
            float2 v2 = bf2f(xr[64 + lane]);
            float2 v3 = bf2f(xr[96 + lane]);
            a0.x += al01.x * v0.x; a0.y += al01.x * v0.y;
            a1.x += al01.y * v1.x; a1.y += al01.y * v1.y;
            a2.x += al23.x * v2.x; a2.y += al23.x * v2.y;
            a3.x += al23.y * v3.x; a3.y += al23.y * v3.y;
        }
        float2 bv = ((const float2*)bias)[lane];
        float hv0 = 0.25f * (a0.x / dn0 + a1.x / dn1 + a2.x / dn2 + a3.x / dn3) + bv.x;
        float hv1 = 0.25f * (a0.y / dn0 + a1.y / dn1 + a2.y / dn2 + a3.y / dn3) + bv.y;
        sHv[wid][2 * lane]     = fmaxf(hv0, 0.f);
        sHv[wid][2 * lane + 1] = fmaxf(hv1, 0.f);
        if (lane == 0) sG[wid] = batch_of(batch, n);
    } else {
        if (lane == 0) sG[wid] = -1;
    }
    __syncthreads();

    // Run-length merge the 8 per-node vectors by graph id; 64 threads, one
    // column each. col==0 thread also carries the node count for d_gcnt.
    if (threadIdx.x < 64) {
        int col = threadIdx.x;
        int curg = -1, cnt = 0;
        float run = 0.f;
#pragma unroll
        for (int w = 0; w < 8; w++) {
            int gw = sG[w];
            if (gw < 0) continue;
            if (gw != curg) {
                if (curg >= 0) {
                    atomicAdd(&d_gsum[curg * 64 + col], run);
                    if (col == 0) atomicAdd(&d_gcnt[curg], cnt);
                }
                curg = gw; run = 0.f; cnt = 0;
            }
            run += sHv[w][col];
            cnt++;
        }
        if (curg >= 0) {
            atomicAdd(&d_gsum[curg * 64 + col], run);
            if (col == 0) atomicAdd(&d_gcnt[curg], cnt);
        }
    }
}

// Head MLP: one block per graph. Also consumer-resets gsum/gcnt/flag32.
__global__ void k_mlp(const float* __restrict__ w1, const float* __restrict__ b1,
                      const float* __restrict__ w2, const float* __restrict__ b2,
                      float* __restrict__ out) {
    __shared__ float sg[64], sz[64];
    int g = blockIdx.x, c = threadIdx.x;
    float cnt = (float)d_gcnt[g];
    if (cnt < 1.f) cnt = 1.f;
    sg[c] = d_gsum[g * 64 + c] / cnt;
    __syncthreads();
    d_gsum[g * 64 + c] = 0.f;                 // consumer-reset
    if (c == 0) d_gcnt[g] = 0;
    if (g == 0 && c == 0) d_flag32 = 0;
    float z = b1[c];
#pragma unroll 16
    for (int k = 0; k < 64; k++) z += sg[k] * w1[k * 64 + c];
    z = fmaxf(z, 0.f);
    sz[c] = z * w2[c];
    __syncthreads();
    if (c < 32) {
        float v = sz[c] + sz[c + 32];
#pragma unroll
        for (int o = 16; o; o >>= 1) v += __shfl_down_sync(0xffffffffu, v, o);
        if (c == 0) out[g] = 1.f / (1.f + expf(-(v + b2[0])));
    }
}

// ---------------- launcher ----------------
extern "C" void kernel_launch(void* const* d_in, const int* in_sizes, int n_in,
                              void* d_out, int out_size) {
    const float* x     = (const float*)d_in[0];
    const float* W     = (const float*)d_in[1];
    const float* att_s = (const float*)d_in[2];
    const float* att_d = (const float*)d_in[3];
    const float* bias  = (const float*)d_in[4];
    const float* w1    = (const float*)d_in[5];
    const float* b1    = (const float*)d_in[6];
    const float* w2    = (const float*)d_in[7];
    const float* b2    = (const float*)d_in[8];
    const void*  ei    = d_in[9];
    const void*  batch = d_in[10];
    float* out = (float*)d_out;

    k_detect<<<64, 256>>>((const uint4*)ei);
    k_wprep<<<(KDIM * HC / 4 + 255) / 256, 256>>>(W);
    k_deg<<<(EE / 2 + 255) / 256, 256>>>(ei);
    k_gemm_tc<<<(NN + BM - 1) / BM, 256>>>(x, att_s, att_d);   // profile slot 4
    int scan_blks = (NN + 1023) / 1024;
    k_scan1<<<scan_blks, 1024>>>();
    k_scan3<<<(NN + 255) / 256, 256>>>(scan_blks);
    k_edge<<<(ENQ + 255) / 256, 256>>>(ei);
    k_agg<<<(NN + 7) / 8, 256>>>(batch, bias);
    k_mlp<<<GGR, 64>>>(w1, b1, w2, b2, out);
}